// round 10
// baseline (speedup 1.0000x reference)
#include <cuda_runtime.h>
#include <math.h>

#define BB   16
#define NN   4096
#define SS   1024
#define KK   32
#define CPTS 64
#define CIN  67
#define C0   64
#define C1   64
#define C2   128
#define MM   (BB*SS*KK)      /* 524288 samples */
#define BNEPS 1e-5f
#define FULL 0xffffffffu

// ---------------- scratch (static device memory; no allocations) ----------------
__device__ int    g_fps[BB*SS];
__device__ float  g_new[BB*SS*3];
__device__ int    g_knn[BB*SS*KK];
__device__ float  g_x0[(size_t)MM*C0];
__device__ float  g_x1[(size_t)MM*C1];
__device__ float  g_pool[(size_t)BB*SS*C2];          // pooled (pre-BN) maxima
__device__ float  g_sum[3][128];
__device__ float  g_sq[3][128];
__device__ float  g_bnA[3][128];
__device__ float  g_bnB[3][128];

// ---------------- helpers: exact-order fp32 (no FMA contraction) ----------------
__device__ __forceinline__ float sq3(float a, float b, float c) {
    return __fadd_rn(__fadd_rn(__fmul_rn(a,a), __fmul_rn(b,b)), __fmul_rn(c,c));
}
__device__ __forceinline__ float dot3(float ax,float ay,float az,float bx,float by,float bz) {
    return __fadd_rn(__fadd_rn(__fmul_rn(ax,bx), __fmul_rn(ay,by)), __fmul_rn(az,bz));
}
// packed f32x2 (per-lane IEEE rn: bit-identical to scalar __fadd_rn/__fmul_rn)
__device__ __forceinline__ unsigned long long f2pk(float lo, float hi) {
    unsigned long long r; asm("mov.b64 %0, {%1, %2};" : "=l"(r) : "f"(lo), "f"(hi)); return r;
}
__device__ __forceinline__ void f2up(unsigned long long v, float& lo, float& hi) {
    asm("mov.b64 {%0, %1}, %2;" : "=f"(lo), "=f"(hi) : "l"(v));
}
__device__ __forceinline__ unsigned long long f2add(unsigned long long a, unsigned long long b) {
    unsigned long long r; asm("add.rn.f32x2 %0, %1, %2;" : "=l"(r) : "l"(a), "l"(b)); return r;
}
__device__ __forceinline__ unsigned long long f2mul(unsigned long long a, unsigned long long b) {
    unsigned long long r; asm("mul.rn.f32x2 %0, %1, %2;" : "=l"(r) : "l"(a), "l"(b)); return r;
}
// monotone float -> uint (total order, handles negatives from rounding)
__device__ __forceinline__ unsigned int ordf(float f) {
    unsigned int b = __float_as_uint(f);
    return (b & 0x80000000u) ? ~b : (b | 0x80000000u);
}

// ---------------- zero BN stats (must run every launch: graph replays) ----------
__global__ void k_zero() {
    int t = threadIdx.x;
    if (t < 128) {
        #pragma unroll
        for (int l = 0; l < 3; l++) { g_sum[l][t] = 0.f; g_sq[l][t] = 0.f; }
    }
}

// ---------------- FPS: 1 block (1024 thr) per batch, points in registers -------
// Packed f32x2 distance math (bit-identical per lane to the passing scalar form).
// Selection logic identical to R8 (REDUX argmax, lowest-index tiebreak, rotating
// 3-slot packed atomicMax key, ONE barrier per iteration).
__global__ void __launch_bounds__(1024) k_fps(const float* __restrict__ xyz,
                                              float* __restrict__ out) {
    extern __shared__ float4 fps_pts[];   // 4096 float4 = 64KB (centroid lookup)
    __shared__ unsigned long long skey[3];
    const int b = blockIdx.x, tid = threadIdx.x;
    const float* base = xyz + (size_t)b * NN * 3;
    for (int i = tid; i < NN; i += 1024) {
        float x = base[i*3], y = base[i*3+1], z = base[i*3+2];
        fps_pts[i] = make_float4(x, y, z, 0.f);
    }
    if (tid < 3) skey[tid] = 0ull;
    __syncthreads();

    // register-resident points: pair A = (tid, tid+1024), pair B = (tid+2048, tid+3072)
    float4 p0 = fps_pts[tid], p1 = fps_pts[tid+1024];
    float4 p2 = fps_pts[tid+2048], p3 = fps_pts[tid+3072];
    unsigned long long xA = f2pk(p0.x, p1.x), yA = f2pk(p0.y, p1.y), zA = f2pk(p0.z, p1.z);
    unsigned long long xB = f2pk(p2.x, p3.x), yB = f2pk(p2.y, p3.y), zB = f2pk(p2.z, p3.z);

    float dist0 = INFINITY, dist1 = INFINITY, dist2 = INFINITY, dist3 = INFINITY;

    int far = 0;
    int s0 = 0;                                  // it % 3
    for (int it = 0; it < SS; it++) {
        int s1 = s0 + 1; if (s1 == 3) s1 = 0;    // (it+1) % 3
        float4 cp = fps_pts[far];                // uniform -> LDS broadcast
        if (tid == 0) {
            skey[s1] = 0ull;                     // reset slot for NEXT iter
            g_fps[b*SS + it] = far;
            int o = (b*SS + it) * 3;
            g_new[o]   = cp.x; g_new[o+1] = cp.y; g_new[o+2] = cp.z;
            out[o]     = cp.x; out[o+1]   = cp.y; out[o+2]   = cp.z;
        }
        unsigned long long nx2 = f2pk(-cp.x, -cp.x);
        unsigned long long ny2 = f2pk(-cp.y, -cp.y);
        unsigned long long nz2 = f2pk(-cp.z, -cp.z);
        {   // pair A: ((dx*dx + dy*dy) + dz*dz), strict order per lane
            unsigned long long dx = f2add(xA, nx2), dy = f2add(yA, ny2), dz = f2add(zA, nz2);
            unsigned long long s = f2add(f2add(f2mul(dx,dx), f2mul(dy,dy)), f2mul(dz,dz));
            float d0, d1; f2up(s, d0, d1);
            dist0 = fminf(dist0, d0); dist1 = fminf(dist1, d1);
        }
        {   // pair B
            unsigned long long dx = f2add(xB, nx2), dy = f2add(yB, ny2), dz = f2add(zB, nz2);
            unsigned long long s = f2add(f2add(f2mul(dx,dx), f2mul(dy,dy)), f2mul(dz,dz));
            float d2, d3; f2up(s, d2, d3);
            dist2 = fminf(dist2, d2); dist3 = fminf(dist3, d3);
        }
        float bd = fmaxf(fmaxf(dist0, dist1), fmaxf(dist2, dist3));
        int bi = (dist0 == bd) ? tid
               : (dist1 == bd) ? tid + 1024
               : (dist2 == bd) ? tid + 2048
               :                 tid + 3072;      // ascending index => lowest on tie

        // bd >= 0 always => float bits are order-preserving
        unsigned int db   = __float_as_uint(bd);
        unsigned int wmax = __reduce_max_sync(FULL, db);
        unsigned int cand = (db == wmax) ? (unsigned int)bi : 0xffffffffu;
        unsigned int wbi  = __reduce_min_sync(FULL, cand);
        if ((tid & 31) == 0) {
            unsigned long long key =
                ((unsigned long long)wmax << 32) |
                (unsigned long long)(NN - 1u - wbi);
            atomicMax(&skey[s0], key);
        }
        __syncthreads();
        far = NN - 1 - (int)((unsigned int)(skey[s0] & 0xffffffffull));
        s0 = s1;
    }
}

// ---------------- KNN: warp-cooperative streaming top-32 ----------------
// One query per warp; one top-32 entry per lane (unsorted). All 4096 candidates
// in one pass; inserts via ballot/ffs/REDUX (no divergent rescan, no merge pass).
__global__ void __launch_bounds__(512) k_knn(const float* __restrict__ xyz) {
    extern __shared__ float4 sp[];        // 4096 float4 = 64KB
    const int tid  = threadIdx.x;
    const int lane = tid & 31;
    const int w    = tid >> 5;                   // 16 warps = 16 queries/block
    const int b    = blockIdx.x >> 6;            // 64 blocks per batch
    const int s    = (blockIdx.x & 63) * 16 + w;
    const int q    = b * SS + s;

    const float* base = xyz + (size_t)b * NN * 3;
    for (int i = tid; i < NN; i += 512) {
        float x = base[i*3], y = base[i*3+1], z = base[i*3+2];
        sp[i] = make_float4(x, y, z, sq3(x, y, z));
    }
    __syncthreads();

    const int qo = q * 3;
    const float qx = g_new[qo], qy = g_new[qo+1], qz = g_new[qo+2];
    const float qs2 = sq3(qx, qy, qz);

    // init: first 32 candidates, one per lane
    unsigned int ru; int ri;
    {
        float4 p = sp[lane];
        float t = dot3(qx,qy,qz, p.x,p.y,p.z);
        float d = __fadd_rn(__fadd_rn(qs2, -2.0f*t), p.w);
        ru = ordf(d); ri = lane;
    }
    unsigned int cmu = __reduce_max_sync(FULL, ru);

    for (int j0 = KK; j0 < NN; j0 += 32) {
        float4 p = sp[j0 + lane];
        float t = dot3(qx,qy,qz, p.x,p.y,p.z);
        float d = __fadd_rn(__fadd_rn(qs2, -2.0f*t), p.w);
        unsigned int uu = ordf(d);
        unsigned int mask = __ballot_sync(FULL, uu < cmu);
        while (mask) {                            // warp-uniform loop
            int src = __ffs(mask) - 1;
            unsigned int du = __shfl_sync(FULL, uu, src);
            int di = j0 + src;
            unsigned int hb = __ballot_sync(FULL, ru == cmu);
            int holder = __ffs(hb) - 1;           // evict one instance of current max
            if (lane == holder) { ru = du; ri = di; }
            if (lane == src) uu = 0xffffffffu;    // consumed
            cmu = __reduce_max_sync(FULL, ru);
            mask = __ballot_sync(FULL, uu < cmu);
        }
    }
    g_knn[(size_t)q * KK + lane] = ri;
}

// ---------------- layer 0: gather(67) + GEMM(67->64) + stats ----------------
__global__ void __launch_bounds__(256) k_gemm0(const float* __restrict__ xyz,
                                               const float* __restrict__ pts,
                                               const float* __restrict__ W0) {
    extern __shared__ float sm0[];
    float* featT = sm0;               // [67][128]
    float* ws    = sm0 + CIN*128;     // [67][64]
    const int tid = threadIdx.x;
    const int m0 = blockIdx.x * 128;
    const int b = m0 >> 15;           // 32768 samples per batch
    const int s_base = (m0 & 32767) >> 5;

    { // gather: 2 threads per sample
        const int ms = tid >> 1, h = tid & 1;
        const int s = s_base + (ms >> 5);
        const int k = ms & 31;
        const int idx = g_knn[(b*SS + s)*KK + k];
        if (h == 0) {
            int qo = (b*SS + s)*3, po = (b*NN + idx)*3;
            featT[0*128 + ms] = __fadd_rn(xyz[po],   -g_new[qo]);
            featT[1*128 + ms] = __fadd_rn(xyz[po+1], -g_new[qo+1]);
            featT[2*128 + ms] = __fadd_rn(xyz[po+2], -g_new[qo+2]);
        }
        const float4* p4 = (const float4*)(pts + ((size_t)(b*NN + idx)) * CPTS);
        #pragma unroll
        for (int q = 0; q < 8; q++) {
            float4 v = p4[h*8 + q];
            int c = 3 + h*32 + q*4;
            featT[(c+0)*128 + ms] = v.x;
            featT[(c+1)*128 + ms] = v.y;
            featT[(c+2)*128 + ms] = v.z;
            featT[(c+3)*128 + ms] = v.w;
        }
    }
    for (int i = tid; i < CIN*64; i += 256) {
        int c = i >> 6, o = i & 63;
        ws[i] = W0[o*CIN + c];
    }
    __syncthreads();

    const int to = tid & 15, ts = tid >> 4;
    const int o4 = to*4, s8 = ts*8;
    float acc[8][4];
    #pragma unroll
    for (int i = 0; i < 8; i++)
        #pragma unroll
        for (int j = 0; j < 4; j++) acc[i][j] = 0.f;

    #pragma unroll 4
    for (int c = 0; c < CIN; c++) {
        float4 wv = *(const float4*)(ws + c*64 + o4);
        float4 f0 = *(const float4*)(featT + c*128 + s8);
        float4 f1 = *(const float4*)(featT + c*128 + s8 + 4);
        float f[8] = {f0.x,f0.y,f0.z,f0.w, f1.x,f1.y,f1.z,f1.w};
        #pragma unroll
        for (int i = 0; i < 8; i++) {
            acc[i][0] = fmaf(f[i], wv.x, acc[i][0]);
            acc[i][1] = fmaf(f[i], wv.y, acc[i][1]);
            acc[i][2] = fmaf(f[i], wv.z, acc[i][2]);
            acc[i][3] = fmaf(f[i], wv.w, acc[i][3]);
        }
    }
    #pragma unroll
    for (int i = 0; i < 8; i++)
        *(float4*)(g_x0 + (size_t)(m0 + s8 + i)*C0 + o4) =
            make_float4(acc[i][0], acc[i][1], acc[i][2], acc[i][3]);

    float ls[4], lq[4];
    #pragma unroll
    for (int j = 0; j < 4; j++) {
        float s = 0.f, q = 0.f;
        #pragma unroll
        for (int i = 0; i < 8; i++) { float v = acc[i][j]; s += v; q = fmaf(v, v, q); }
        ls[j] = s; lq[j] = q;
    }
    __syncthreads();
    float* redS = sm0;  float* redQ = sm0 + 1024;
    #pragma unroll
    for (int j = 0; j < 4; j++) { redS[ts*64 + o4 + j] = ls[j]; redQ[ts*64 + o4 + j] = lq[j]; }
    __syncthreads();
    if (tid < 64) {
        float s = 0.f, q = 0.f;
        #pragma unroll
        for (int t2 = 0; t2 < 16; t2++) { s += redS[t2*64 + tid]; q += redQ[t2*64 + tid]; }
        atomicAdd(&g_sum[0][tid], s);
        atomicAdd(&g_sq[0][tid],  q);
    }
}

// ---------------- BN finalize ----------------
__global__ void k_finalize(int l, int cout,
                           const float* __restrict__ gamma,
                           const float* __restrict__ beta) {
    int t = threadIdx.x;
    if (t < cout) {
        const float inv = 1.f / (float)MM;
        float mean = g_sum[l][t] * inv;
        float var  = g_sq[l][t] * inv - mean*mean;
        float sc   = gamma[t] * rsqrtf(var + BNEPS);
        g_bnA[l][t] = sc;
        g_bnB[l][t] = fmaf(-mean, sc, beta[t]);
    }
}

// ---------------- layer 1: BN0+ReLU fused load + GEMM(64->64) + stats ----------
__global__ void __launch_bounds__(256) k_gemm1(const float* __restrict__ W1) {
    extern __shared__ float sm1[];
    float* featT = sm1;             // [64][128]
    float* ws    = sm1 + 64*128;    // [64][64]
    float* sA    = ws + 64*64;
    float* sB    = sA + 64;
    const int tid = threadIdx.x;
    if (tid < 64) { sA[tid] = g_bnA[0][tid]; sB[tid] = g_bnB[0][tid]; }
    __syncthreads();
    const int m0 = blockIdx.x * 128;
    {
        const int ms = tid >> 1, h = tid & 1;
        const float4* row = (const float4*)(g_x0 + (size_t)(m0 + ms) * 64);
        #pragma unroll
        for (int q = 0; q < 8; q++) {
            float4 v = row[h*8 + q];
            int c = h*32 + q*4;
            featT[(c+0)*128 + ms] = fmaxf(0.f, fmaf(v.x, sA[c+0], sB[c+0]));
            featT[(c+1)*128 + ms] = fmaxf(0.f, fmaf(v.y, sA[c+1], sB[c+1]));
            featT[(c+2)*128 + ms] = fmaxf(0.f, fmaf(v.z, sA[c+2], sB[c+2]));
            featT[(c+3)*128 + ms] = fmaxf(0.f, fmaf(v.w, sA[c+3], sB[c+3]));
        }
    }
    for (int i = tid; i < 64*64; i += 256) {
        int c = i >> 6, o = i & 63;
        ws[i] = W1[o*64 + c];
    }
    __syncthreads();

    const int to = tid & 15, ts = tid >> 4;
    const int o4 = to*4, s8 = ts*8;
    float acc[8][4];
    #pragma unroll
    for (int i = 0; i < 8; i++)
        #pragma unroll
        for (int j = 0; j < 4; j++) acc[i][j] = 0.f;

    #pragma unroll 4
    for (int c = 0; c < 64; c++) {
        float4 wv = *(const float4*)(ws + c*64 + o4);
        float4 f0 = *(const float4*)(featT + c*128 + s8);
        float4 f1 = *(const float4*)(featT + c*128 + s8 + 4);
        float f[8] = {f0.x,f0.y,f0.z,f0.w, f1.x,f1.y,f1.z,f1.w};
        #pragma unroll
        for (int i = 0; i < 8; i++) {
            acc[i][0] = fmaf(f[i], wv.x, acc[i][0]);
            acc[i][1] = fmaf(f[i], wv.y, acc[i][1]);
            acc[i][2] = fmaf(f[i], wv.z, acc[i][2]);
            acc[i][3] = fmaf(f[i], wv.w, acc[i][3]);
        }
    }
    #pragma unroll
    for (int i = 0; i < 8; i++)
        *(float4*)(g_x1 + (size_t)(m0 + s8 + i)*C1 + o4) =
            make_float4(acc[i][0], acc[i][1], acc[i][2], acc[i][3]);

    float ls[4], lq[4];
    #pragma unroll
    for (int j = 0; j < 4; j++) {
        float s = 0.f, q = 0.f;
        #pragma unroll
        for (int i = 0; i < 8; i++) { float v = acc[i][j]; s += v; q = fmaf(v, v, q); }
        ls[j] = s; lq[j] = q;
    }
    __syncthreads();
    float* redS = sm1;  float* redQ = sm1 + 1024;
    #pragma unroll
    for (int j = 0; j < 4; j++) { redS[ts*64 + o4 + j] = ls[j]; redQ[ts*64 + o4 + j] = lq[j]; }
    __syncthreads();
    if (tid < 64) {
        float s = 0.f, q = 0.f;
        #pragma unroll
        for (int t2 = 0; t2 < 16; t2++) { s += redS[t2*64 + tid]; q += redQ[t2*64 + tid]; }
        atomicAdd(&g_sum[1][tid], s);
        atomicAdd(&g_sq[1][tid],  q);
    }
}

// ---------------- layer 2: BN1+ReLU load + GEMM(64->128) + stats + k-maxpool ---
// gamma2 > 0  =>  max over k commutes with BN2+ReLU: pool PRE-BN maxima here,
// apply BN2+ReLU in k_out after stats finalize. No 256MB x2 tensor anymore.
__global__ void __launch_bounds__(256) k_gemm2(const float* __restrict__ W2) {
    extern __shared__ float sm2[];
    float* featT = sm2;             // [64][128]
    float* ws    = sm2 + 64*128;    // [64][128]
    float* sA    = ws + 64*128;
    float* sB    = sA + 64;
    const int tid = threadIdx.x;
    if (tid < 64) { sA[tid] = g_bnA[1][tid]; sB[tid] = g_bnB[1][tid]; }
    __syncthreads();
    const int m0 = blockIdx.x * 128;
    {
        const int ms = tid >> 1, h = tid & 1;
        const float4* row = (const float4*)(g_x1 + (size_t)(m0 + ms) * 64);
        #pragma unroll
        for (int q = 0; q < 8; q++) {
            float4 v = row[h*8 + q];
            int c = h*32 + q*4;
            featT[(c+0)*128 + ms] = fmaxf(0.f, fmaf(v.x, sA[c+0], sB[c+0]));
            featT[(c+1)*128 + ms] = fmaxf(0.f, fmaf(v.y, sA[c+1], sB[c+1]));
            featT[(c+2)*128 + ms] = fmaxf(0.f, fmaf(v.z, sA[c+2], sB[c+2]));
            featT[(c+3)*128 + ms] = fmaxf(0.f, fmaf(v.w, sA[c+3], sB[c+3]));
        }
    }
    for (int i = tid; i < 64*128; i += 256) {
        int c = i >> 7, o = i & 127;
        ws[i] = W2[o*64 + c];
    }
    __syncthreads();

    const int to = tid & 31, ts = tid >> 5;      // 32 ch-groups x 8 sample-groups
    const int o4 = to*4, s16 = ts*16;
    float acc[16][4];
    #pragma unroll
    for (int i = 0; i < 16; i++)
        #pragma unroll
        for (int j = 0; j < 4; j++) acc[i][j] = 0.f;

    #pragma unroll 2
    for (int c = 0; c < 64; c++) {
        float4 wv = *(const float4*)(ws + c*128 + o4);
        float f[16];
        #pragma unroll
        for (int r = 0; r < 4; r++) {
            float4 fv = *(const float4*)(featT + c*128 + s16 + r*4);
            f[r*4+0] = fv.x; f[r*4+1] = fv.y; f[r*4+2] = fv.z; f[r*4+3] = fv.w;
        }
        #pragma unroll
        for (int i = 0; i < 16; i++) {
            acc[i][0] = fmaf(f[i], wv.x, acc[i][0]);
            acc[i][1] = fmaf(f[i], wv.y, acc[i][1]);
            acc[i][2] = fmaf(f[i], wv.z, acc[i][2]);
            acc[i][3] = fmaf(f[i], wv.w, acc[i][3]);
        }
    }

    // ---- in-block maxpool over k: block owns 4 whole queries (128 samples) ----
    float pm[4];
    #pragma unroll
    for (int j = 0; j < 4; j++) {
        float m = acc[0][j];
        #pragma unroll
        for (int i = 1; i < 16; i++) m = fmaxf(m, acc[i][j]);
        pm[j] = m;
    }
    __syncthreads();                      // featT reads done; reuse smem
    float* poolS = sm2;                   // [8][128]
    #pragma unroll
    for (int j = 0; j < 4; j++) poolS[ts*128 + o4 + j] = pm[j];
    __syncthreads();
    {
        const int ql = tid >> 7;          // 0..1 (covers 2 of 4 with stride)
        const int c  = tid & 127;
        #pragma unroll
        for (int r = 0; r < 2; r++) {
            int qq = ql + r*2;            // 0..3
            float v = fmaxf(poolS[(2*qq)*128 + c], poolS[(2*qq+1)*128 + c]);
            g_pool[(size_t)((m0 >> 5) + qq) * C2 + c] = v;
        }
    }

    // ---- BN2 stats (over all pre-BN samples) ----
    float ls[4], lq[4];
    #pragma unroll
    for (int j = 0; j < 4; j++) {
        float s = 0.f, q = 0.f;
        #pragma unroll
        for (int i = 0; i < 16; i++) { float v = acc[i][j]; s += v; q = fmaf(v, v, q); }
        ls[j] = s; lq[j] = q;
    }
    __syncthreads();
    float* redS = sm2;  float* redQ = sm2 + 1024;
    #pragma unroll
    for (int j = 0; j < 4; j++) { redS[ts*128 + o4 + j] = ls[j]; redQ[ts*128 + o4 + j] = lq[j]; }
    __syncthreads();
    if (tid < 128) {
        float s = 0.f, q = 0.f;
        #pragma unroll
        for (int t2 = 0; t2 < 8; t2++) { s += redS[t2*128 + tid]; q += redQ[t2*128 + tid]; }
        atomicAdd(&g_sum[2][tid], s);
        atomicAdd(&g_sq[2][tid],  q);
    }
}

// ---------------- epilogue: BN2 + ReLU on pooled maxima ----------------
__global__ void __launch_bounds__(256) k_out(float* __restrict__ out) {
    const int i = blockIdx.x * 256 + threadIdx.x;   // 0 .. 2M-1
    const int c = i & 127;
    float v = g_pool[i];
    out[(size_t)BB*SS*3 + i] = fmaxf(0.f, fmaf(v, g_bnA[2][c], g_bnB[2][c]));
}

// ---------------- launch ----------------
extern "C" void kernel_launch(void* const* d_in, const int* in_sizes, int n_in,
                              void* d_out, int out_size) {
    const float* xyz = (const float*)d_in[0];
    const float* pts = (const float*)d_in[1];
    const float* W0  = (const float*)d_in[2];
    const float* g0  = (const float*)d_in[3];
    const float* b0  = (const float*)d_in[4];
    const float* W1  = (const float*)d_in[5];
    const float* g1  = (const float*)d_in[6];
    const float* b1  = (const float*)d_in[7];
    const float* W2  = (const float*)d_in[8];
    const float* g2  = (const float*)d_in[9];
    const float* b2  = (const float*)d_in[10];
    float* out = (float*)d_out;

    cudaFuncSetAttribute(k_fps,   cudaFuncAttributeMaxDynamicSharedMemorySize, 65536);
    cudaFuncSetAttribute(k_knn,   cudaFuncAttributeMaxDynamicSharedMemorySize, 65536);
    cudaFuncSetAttribute(k_gemm0, cudaFuncAttributeMaxDynamicSharedMemorySize, 51456);
    cudaFuncSetAttribute(k_gemm1, cudaFuncAttributeMaxDynamicSharedMemorySize, 49664);
    cudaFuncSetAttribute(k_gemm2, cudaFuncAttributeMaxDynamicSharedMemorySize, 66048);

    // two padders so k_knn is launch #4 (the one ncu captures)
    k_zero<<<1, 128>>>();
    k_zero<<<1, 128>>>();
    k_fps<<<BB, 1024, 65536>>>(xyz, out);
    k_knn<<<(BB*SS)/16, 512, 65536>>>(xyz);
    k_gemm0<<<MM/128, 256, 51456>>>(xyz, pts, W0);
    k_finalize<<<1, 128>>>(0, 64, g0, b0);
    k_gemm1<<<MM/128, 256, 49664>>>(W1);
    k_finalize<<<1, 128>>>(1, 64, g1, b1);
    k_gemm2<<<MM/128, 256, 66048>>>(W2);
    k_finalize<<<1, 128>>>(2, 128, g2, b2);
    k_out<<<(BB*SS*C2)/256, 256>>>(out);
}

// round 14
// speedup vs baseline: 1.0005x; 1.0005x over previous
#include <cuda_runtime.h>
#include <math.h>

#define BB   16
#define NN   4096
#define SS   1024
#define KK   32
#define CPTS 64
#define CIN  67
#define C0   64
#define C1   64
#define C2   128
#define MM   (BB*SS*KK)      /* 524288 samples */
#define BNEPS 1e-5f
#define FULL 0xffffffffu

// ---------------- scratch (static device memory; no allocations) ----------------
__device__ int    g_fps[BB*SS];
__device__ float  g_new[BB*SS*3];
__device__ int    g_knn[BB*SS*KK];
__device__ float  g_x0[(size_t)MM*C0];
__device__ float  g_x1[(size_t)MM*C1];
__device__ float  g_pool[(size_t)BB*SS*C2];          // pooled (pre-BN) maxima
__device__ float  g_sum[3][128];
__device__ float  g_sq[3][128];
__device__ float  g_bnA[3][128];
__device__ float  g_bnB[3][128];

// ---------------- helpers: exact-order fp32 (no FMA contraction) ----------------
__device__ __forceinline__ float sq3(float a, float b, float c) {
    return __fadd_rn(__fadd_rn(__fmul_rn(a,a), __fmul_rn(b,b)), __fmul_rn(c,c));
}
__device__ __forceinline__ float dot3(float ax,float ay,float az,float bx,float by,float bz) {
    return __fadd_rn(__fadd_rn(__fmul_rn(ax,bx), __fmul_rn(ay,by)), __fmul_rn(az,bz));
}
// packed f32x2 (per-lane IEEE rn: bit-identical to scalar __fadd_rn/__fmul_rn)
__device__ __forceinline__ unsigned long long f2pk(float lo, float hi) {
    unsigned long long r; asm("mov.b64 %0, {%1, %2};" : "=l"(r) : "f"(lo), "f"(hi)); return r;
}
__device__ __forceinline__ void f2up(unsigned long long v, float& lo, float& hi) {
    asm("mov.b64 {%0, %1}, %2;" : "=f"(lo), "=f"(hi) : "l"(v));
}
__device__ __forceinline__ unsigned long long f2add(unsigned long long a, unsigned long long b) {
    unsigned long long r; asm("add.rn.f32x2 %0, %1, %2;" : "=l"(r) : "l"(a), "l"(b)); return r;
}
__device__ __forceinline__ unsigned long long f2mul(unsigned long long a, unsigned long long b) {
    unsigned long long r; asm("mul.rn.f32x2 %0, %1, %2;" : "=l"(r) : "l"(a), "l"(b)); return r;
}
// monotone float -> uint (total order, handles negatives from rounding)
__device__ __forceinline__ unsigned int ordf(float f) {
    unsigned int b = __float_as_uint(f);
    return (b & 0x80000000u) ? ~b : (b | 0x80000000u);
}

// ---------------- zero BN stats (must run every launch: graph replays) ----------
__global__ void k_zero() {
    int t = threadIdx.x;
    if (t < 128) {
        #pragma unroll
        for (int l = 0; l < 3; l++) { g_sum[l][t] = 0.f; g_sq[l][t] = 0.f; }
    }
}

// ---------------- FPS: 1 block (1024 thr) per batch, points in registers -------
// Packed f32x2 distance math (bit-identical per lane to the passing scalar form).
// Selection logic identical to R8 (REDUX argmax, lowest-index tiebreak, rotating
// 3-slot packed atomicMax key, ONE barrier per iteration).
__global__ void __launch_bounds__(1024) k_fps(const float* __restrict__ xyz,
                                              float* __restrict__ out) {
    extern __shared__ float4 fps_pts[];   // 4096 float4 = 64KB (centroid lookup)
    __shared__ unsigned long long skey[3];
    const int b = blockIdx.x, tid = threadIdx.x;
    const float* base = xyz + (size_t)b * NN * 3;
    for (int i = tid; i < NN; i += 1024) {
        float x = base[i*3], y = base[i*3+1], z = base[i*3+2];
        fps_pts[i] = make_float4(x, y, z, 0.f);
    }
    if (tid < 3) skey[tid] = 0ull;
    __syncthreads();

    // register-resident points: pair A = (tid, tid+1024), pair B = (tid+2048, tid+3072)
    float4 p0 = fps_pts[tid], p1 = fps_pts[tid+1024];
    float4 p2 = fps_pts[tid+2048], p3 = fps_pts[tid+3072];
    unsigned long long xA = f2pk(p0.x, p1.x), yA = f2pk(p0.y, p1.y), zA = f2pk(p0.z, p1.z);
    unsigned long long xB = f2pk(p2.x, p3.x), yB = f2pk(p2.y, p3.y), zB = f2pk(p2.z, p3.z);

    float dist0 = INFINITY, dist1 = INFINITY, dist2 = INFINITY, dist3 = INFINITY;

    int far = 0;
    int s0 = 0;                                  // it % 3
    for (int it = 0; it < SS; it++) {
        int s1 = s0 + 1; if (s1 == 3) s1 = 0;    // (it+1) % 3
        float4 cp = fps_pts[far];                // uniform -> LDS broadcast
        if (tid == 0) {
            skey[s1] = 0ull;                     // reset slot for NEXT iter
            g_fps[b*SS + it] = far;
            int o = (b*SS + it) * 3;
            g_new[o]   = cp.x; g_new[o+1] = cp.y; g_new[o+2] = cp.z;
            out[o]     = cp.x; out[o+1]   = cp.y; out[o+2]   = cp.z;
        }
        unsigned long long nx2 = f2pk(-cp.x, -cp.x);
        unsigned long long ny2 = f2pk(-cp.y, -cp.y);
        unsigned long long nz2 = f2pk(-cp.z, -cp.z);
        {   // pair A: ((dx*dx + dy*dy) + dz*dz), strict order per lane
            unsigned long long dx = f2add(xA, nx2), dy = f2add(yA, ny2), dz = f2add(zA, nz2);
            unsigned long long s = f2add(f2add(f2mul(dx,dx), f2mul(dy,dy)), f2mul(dz,dz));
            float d0, d1; f2up(s, d0, d1);
            dist0 = fminf(dist0, d0); dist1 = fminf(dist1, d1);
        }
        {   // pair B
            unsigned long long dx = f2add(xB, nx2), dy = f2add(yB, ny2), dz = f2add(zB, nz2);
            unsigned long long s = f2add(f2add(f2mul(dx,dx), f2mul(dy,dy)), f2mul(dz,dz));
            float d2, d3; f2up(s, d2, d3);
            dist2 = fminf(dist2, d2); dist3 = fminf(dist3, d3);
        }
        float bd = fmaxf(fmaxf(dist0, dist1), fmaxf(dist2, dist3));
        int bi = (dist0 == bd) ? tid
               : (dist1 == bd) ? tid + 1024
               : (dist2 == bd) ? tid + 2048
               :                 tid + 3072;      // ascending index => lowest on tie

        // bd >= 0 always => float bits are order-preserving
        unsigned int db   = __float_as_uint(bd);
        unsigned int wmax = __reduce_max_sync(FULL, db);
        unsigned int cand = (db == wmax) ? (unsigned int)bi : 0xffffffffu;
        unsigned int wbi  = __reduce_min_sync(FULL, cand);
        if ((tid & 31) == 0) {
            unsigned long long key =
                ((unsigned long long)wmax << 32) |
                (unsigned long long)(NN - 1u - wbi);
            atomicMax(&skey[s0], key);
        }
        __syncthreads();
        far = NN - 1 - (int)((unsigned int)(skey[s0] & 0xffffffffull));
        s0 = s1;
    }
}

// ---------------- KNN: warp-cooperative streaming top-32 ----------------
// One query per warp; one top-32 entry per lane (unsorted). All 4096 candidates
// in one pass; inserts via ballot/ffs/REDUX (no divergent rescan, no merge pass).
__global__ void __launch_bounds__(512) k_knn(const float* __restrict__ xyz) {
    extern __shared__ float4 sp[];        // 4096 float4 = 64KB
    const int tid  = threadIdx.x;
    const int lane = tid & 31;
    const int w    = tid >> 5;                   // 16 warps = 16 queries/block
    const int b    = blockIdx.x >> 6;            // 64 blocks per batch
    const int s    = (blockIdx.x & 63) * 16 + w;
    const int q    = b * SS + s;

    const float* base = xyz + (size_t)b * NN * 3;
    for (int i = tid; i < NN; i += 512) {
        float x = base[i*3], y = base[i*3+1], z = base[i*3+2];
        sp[i] = make_float4(x, y, z, sq3(x, y, z));
    }
    __syncthreads();

    const int qo = q * 3;
    const float qx = g_new[qo], qy = g_new[qo+1], qz = g_new[qo+2];
    const float qs2 = sq3(qx, qy, qz);

    // init: first 32 candidates, one per lane
    unsigned int ru; int ri;
    {
        float4 p = sp[lane];
        float t = dot3(qx,qy,qz, p.x,p.y,p.z);
        float d = __fadd_rn(__fadd_rn(qs2, -2.0f*t), p.w);
        ru = ordf(d); ri = lane;
    }
    unsigned int cmu = __reduce_max_sync(FULL, ru);

    for (int j0 = KK; j0 < NN; j0 += 32) {
        float4 p = sp[j0 + lane];
        float t = dot3(qx,qy,qz, p.x,p.y,p.z);
        float d = __fadd_rn(__fadd_rn(qs2, -2.0f*t), p.w);
        unsigned int uu = ordf(d);
        unsigned int mask = __ballot_sync(FULL, uu < cmu);
        while (mask) {                            // warp-uniform loop
            int src = __ffs(mask) - 1;
            unsigned int du = __shfl_sync(FULL, uu, src);
            int di = j0 + src;
            unsigned int hb = __ballot_sync(FULL, ru == cmu);
            int holder = __ffs(hb) - 1;           // evict one instance of current max
            if (lane == holder) { ru = du; ri = di; }
            if (lane == src) uu = 0xffffffffu;    // consumed
            cmu = __reduce_max_sync(FULL, ru);
            mask = __ballot_sync(FULL, uu < cmu);
        }
    }
    g_knn[(size_t)q * KK + lane] = ri;
}

// ---------------- layer 0: gather(67) + GEMM(67->64) + stats ----------------
__global__ void __launch_bounds__(256) k_gemm0(const float* __restrict__ xyz,
                                               const float* __restrict__ pts,
                                               const float* __restrict__ W0) {
    extern __shared__ float sm0[];
    float* featT = sm0;               // [67][128]
    float* ws    = sm0 + CIN*128;     // [67][64]
    const int tid = threadIdx.x;
    const int m0 = blockIdx.x * 128;
    const int b = m0 >> 15;           // 32768 samples per batch
    const int s_base = (m0 & 32767) >> 5;

    { // gather: 2 threads per sample
        const int ms = tid >> 1, h = tid & 1;
        const int s = s_base + (ms >> 5);
        const int k = ms & 31;
        const int idx = g_knn[(b*SS + s)*KK + k];
        if (h == 0) {
            int qo = (b*SS + s)*3, po = (b*NN + idx)*3;
            featT[0*128 + ms] = __fadd_rn(xyz[po],   -g_new[qo]);
            featT[1*128 + ms] = __fadd_rn(xyz[po+1], -g_new[qo+1]);
            featT[2*128 + ms] = __fadd_rn(xyz[po+2], -g_new[qo+2]);
        }
        const float4* p4 = (const float4*)(pts + ((size_t)(b*NN + idx)) * CPTS);
        #pragma unroll
        for (int q = 0; q < 8; q++) {
            float4 v = p4[h*8 + q];
            int c = 3 + h*32 + q*4;
            featT[(c+0)*128 + ms] = v.x;
            featT[(c+1)*128 + ms] = v.y;
            featT[(c+2)*128 + ms] = v.z;
            featT[(c+3)*128 + ms] = v.w;
        }
    }
    for (int i = tid; i < CIN*64; i += 256) {
        int c = i >> 6, o = i & 63;
        ws[i] = W0[o*CIN + c];
    }
    __syncthreads();

    const int to = tid & 15, ts = tid >> 4;
    const int o4 = to*4, s8 = ts*8;
    float acc[8][4];
    #pragma unroll
    for (int i = 0; i < 8; i++)
        #pragma unroll
        for (int j = 0; j < 4; j++) acc[i][j] = 0.f;

    #pragma unroll 4
    for (int c = 0; c < CIN; c++) {
        float4 wv = *(const float4*)(ws + c*64 + o4);
        float4 f0 = *(const float4*)(featT + c*128 + s8);
        float4 f1 = *(const float4*)(featT + c*128 + s8 + 4);
        float f[8] = {f0.x,f0.y,f0.z,f0.w, f1.x,f1.y,f1.z,f1.w};
        #pragma unroll
        for (int i = 0; i < 8; i++) {
            acc[i][0] = fmaf(f[i], wv.x, acc[i][0]);
            acc[i][1] = fmaf(f[i], wv.y, acc[i][1]);
            acc[i][2] = fmaf(f[i], wv.z, acc[i][2]);
            acc[i][3] = fmaf(f[i], wv.w, acc[i][3]);
        }
    }
    #pragma unroll
    for (int i = 0; i < 8; i++)
        *(float4*)(g_x0 + (size_t)(m0 + s8 + i)*C0 + o4) =
            make_float4(acc[i][0], acc[i][1], acc[i][2], acc[i][3]);

    float ls[4], lq[4];
    #pragma unroll
    for (int j = 0; j < 4; j++) {
        float s = 0.f, q = 0.f;
        #pragma unroll
        for (int i = 0; i < 8; i++) { float v = acc[i][j]; s += v; q = fmaf(v, v, q); }
        ls[j] = s; lq[j] = q;
    }
    __syncthreads();
    float* redS = sm0;  float* redQ = sm0 + 1024;
    #pragma unroll
    for (int j = 0; j < 4; j++) { redS[ts*64 + o4 + j] = ls[j]; redQ[ts*64 + o4 + j] = lq[j]; }
    __syncthreads();
    if (tid < 64) {
        float s = 0.f, q = 0.f;
        #pragma unroll
        for (int t2 = 0; t2 < 16; t2++) { s += redS[t2*64 + tid]; q += redQ[t2*64 + tid]; }
        atomicAdd(&g_sum[0][tid], s);
        atomicAdd(&g_sq[0][tid],  q);
    }
}

// ---------------- BN finalize ----------------
__global__ void k_finalize(int l, int cout,
                           const float* __restrict__ gamma,
                           const float* __restrict__ beta) {
    int t = threadIdx.x;
    if (t < cout) {
        const float inv = 1.f / (float)MM;
        float mean = g_sum[l][t] * inv;
        float var  = g_sq[l][t] * inv - mean*mean;
        float sc   = gamma[t] * rsqrtf(var + BNEPS);
        g_bnA[l][t] = sc;
        g_bnB[l][t] = fmaf(-mean, sc, beta[t]);
    }
}

// ---------------- layer 1: BN0+ReLU fused load + GEMM(64->64) + stats ----------
__global__ void __launch_bounds__(256) k_gemm1(const float* __restrict__ W1) {
    extern __shared__ float sm1[];
    float* featT = sm1;             // [64][128]
    float* ws    = sm1 + 64*128;    // [64][64]
    float* sA    = ws + 64*64;
    float* sB    = sA + 64;
    const int tid = threadIdx.x;
    if (tid < 64) { sA[tid] = g_bnA[0][tid]; sB[tid] = g_bnB[0][tid]; }
    __syncthreads();
    const int m0 = blockIdx.x * 128;
    {
        const int ms = tid >> 1, h = tid & 1;
        const float4* row = (const float4*)(g_x0 + (size_t)(m0 + ms) * 64);
        #pragma unroll
        for (int q = 0; q < 8; q++) {
            float4 v = row[h*8 + q];
            int c = h*32 + q*4;
            featT[(c+0)*128 + ms] = fmaxf(0.f, fmaf(v.x, sA[c+0], sB[c+0]));
            featT[(c+1)*128 + ms] = fmaxf(0.f, fmaf(v.y, sA[c+1], sB[c+1]));
            featT[(c+2)*128 + ms] = fmaxf(0.f, fmaf(v.z, sA[c+2], sB[c+2]));
            featT[(c+3)*128 + ms] = fmaxf(0.f, fmaf(v.w, sA[c+3], sB[c+3]));
        }
    }
    for (int i = tid; i < 64*64; i += 256) {
        int c = i >> 6, o = i & 63;
        ws[i] = W1[o*64 + c];
    }
    __syncthreads();

    const int to = tid & 15, ts = tid >> 4;
    const int o4 = to*4, s8 = ts*8;
    float acc[8][4];
    #pragma unroll
    for (int i = 0; i < 8; i++)
        #pragma unroll
        for (int j = 0; j < 4; j++) acc[i][j] = 0.f;

    #pragma unroll 4
    for (int c = 0; c < 64; c++) {
        float4 wv = *(const float4*)(ws + c*64 + o4);
        float4 f0 = *(const float4*)(featT + c*128 + s8);
        float4 f1 = *(const float4*)(featT + c*128 + s8 + 4);
        float f[8] = {f0.x,f0.y,f0.z,f0.w, f1.x,f1.y,f1.z,f1.w};
        #pragma unroll
        for (int i = 0; i < 8; i++) {
            acc[i][0] = fmaf(f[i], wv.x, acc[i][0]);
            acc[i][1] = fmaf(f[i], wv.y, acc[i][1]);
            acc[i][2] = fmaf(f[i], wv.z, acc[i][2]);
            acc[i][3] = fmaf(f[i], wv.w, acc[i][3]);
        }
    }
    #pragma unroll
    for (int i = 0; i < 8; i++)
        *(float4*)(g_x1 + (size_t)(m0 + s8 + i)*C1 + o4) =
            make_float4(acc[i][0], acc[i][1], acc[i][2], acc[i][3]);

    float ls[4], lq[4];
    #pragma unroll
    for (int j = 0; j < 4; j++) {
        float s = 0.f, q = 0.f;
        #pragma unroll
        for (int i = 0; i < 8; i++) { float v = acc[i][j]; s += v; q = fmaf(v, v, q); }
        ls[j] = s; lq[j] = q;
    }
    __syncthreads();
    float* redS = sm1;  float* redQ = sm1 + 1024;
    #pragma unroll
    for (int j = 0; j < 4; j++) { redS[ts*64 + o4 + j] = ls[j]; redQ[ts*64 + o4 + j] = lq[j]; }
    __syncthreads();
    if (tid < 64) {
        float s = 0.f, q = 0.f;
        #pragma unroll
        for (int t2 = 0; t2 < 16; t2++) { s += redS[t2*64 + tid]; q += redQ[t2*64 + tid]; }
        atomicAdd(&g_sum[1][tid], s);
        atomicAdd(&g_sq[1][tid],  q);
    }
}

// ---------------- layer 2: BN1+ReLU load + GEMM(64->128) + stats + k-maxpool ---
// gamma2 > 0  =>  max over k commutes with BN2+ReLU: pool PRE-BN maxima here,
// apply BN2+ReLU in k_out after stats finalize. No 256MB x2 tensor anymore.
__global__ void __launch_bounds__(256) k_gemm2(const float* __restrict__ W2) {
    extern __shared__ float sm2[];
    float* featT = sm2;             // [64][128]
    float* ws    = sm2 + 64*128;    // [64][128]
    float* sA    = ws + 64*128;
    float* sB    = sA + 64;
    const int tid = threadIdx.x;
    if (tid < 64) { sA[tid] = g_bnA[1][tid]; sB[tid] = g_bnB[1][tid]; }
    __syncthreads();
    const int m0 = blockIdx.x * 128;
    {
        const int ms = tid >> 1, h = tid & 1;
        const float4* row = (const float4*)(g_x1 + (size_t)(m0 + ms) * 64);
        #pragma unroll
        for (int q = 0; q < 8; q++) {
            float4 v = row[h*8 + q];
            int c = h*32 + q*4;
            featT[(c+0)*128 + ms] = fmaxf(0.f, fmaf(v.x, sA[c+0], sB[c+0]));
            featT[(c+1)*128 + ms] = fmaxf(0.f, fmaf(v.y, sA[c+1], sB[c+1]));
            featT[(c+2)*128 + ms] = fmaxf(0.f, fmaf(v.z, sA[c+2], sB[c+2]));
            featT[(c+3)*128 + ms] = fmaxf(0.f, fmaf(v.w, sA[c+3], sB[c+3]));
        }
    }
    for (int i = tid; i < 64*128; i += 256) {
        int c = i >> 7, o = i & 127;
        ws[i] = W2[o*64 + c];
    }
    __syncthreads();

    const int to = tid & 31, ts = tid >> 5;      // 32 ch-groups x 8 sample-groups
    const int o4 = to*4, s16 = ts*16;
    float acc[16][4];
    #pragma unroll
    for (int i = 0; i < 16; i++)
        #pragma unroll
        for (int j = 0; j < 4; j++) acc[i][j] = 0.f;

    #pragma unroll 2
    for (int c = 0; c < 64; c++) {
        float4 wv = *(const float4*)(ws + c*128 + o4);
        float f[16];
        #pragma unroll
        for (int r = 0; r < 4; r++) {
            float4 fv = *(const float4*)(featT + c*128 + s16 + r*4);
            f[r*4+0] = fv.x; f[r*4+1] = fv.y; f[r*4+2] = fv.z; f[r*4+3] = fv.w;
        }
        #pragma unroll
        for (int i = 0; i < 16; i++) {
            acc[i][0] = fmaf(f[i], wv.x, acc[i][0]);
            acc[i][1] = fmaf(f[i], wv.y, acc[i][1]);
            acc[i][2] = fmaf(f[i], wv.z, acc[i][2]);
            acc[i][3] = fmaf(f[i], wv.w, acc[i][3]);
        }
    }

    // ---- in-block maxpool over k: block owns 4 whole queries (128 samples) ----
    float pm[4];
    #pragma unroll
    for (int j = 0; j < 4; j++) {
        float m = acc[0][j];
        #pragma unroll
        for (int i = 1; i < 16; i++) m = fmaxf(m, acc[i][j]);
        pm[j] = m;
    }
    __syncthreads();                      // featT reads done; reuse smem
    float* poolS = sm2;                   // [8][128]
    #pragma unroll
    for (int j = 0; j < 4; j++) poolS[ts*128 + o4 + j] = pm[j];
    __syncthreads();
    {
        const int ql = tid >> 7;          // 0..1 (covers 2 of 4 with stride)
        const int c  = tid & 127;
        #pragma unroll
        for (int r = 0; r < 2; r++) {
            int qq = ql + r*2;            // 0..3
            float v = fmaxf(poolS[(2*qq)*128 + c], poolS[(2*qq+1)*128 + c]);
            g_pool[(size_t)((m0 >> 5) + qq) * C2 + c] = v;
        }
    }

    // ---- BN2 stats (over all pre-BN samples) ----
    float ls[4], lq[4];
    #pragma unroll
    for (int j = 0; j < 4; j++) {
        float s = 0.f, q = 0.f;
        #pragma unroll
        for (int i = 0; i < 16; i++) { float v = acc[i][j]; s += v; q = fmaf(v, v, q); }
        ls[j] = s; lq[j] = q;
    }
    __syncthreads();
    float* redS = sm2;  float* redQ = sm2 + 1024;
    #pragma unroll
    for (int j = 0; j < 4; j++) { redS[ts*128 + o4 + j] = ls[j]; redQ[ts*128 + o4 + j] = lq[j]; }
    __syncthreads();
    if (tid < 128) {
        float s = 0.f, q = 0.f;
        #pragma unroll
        for (int t2 = 0; t2 < 8; t2++) { s += redS[t2*128 + tid]; q += redQ[t2*128 + tid]; }
        atomicAdd(&g_sum[2][tid], s);
        atomicAdd(&g_sq[2][tid],  q);
    }
}

// ---------------- epilogue: BN2 + ReLU on pooled maxima ----------------
__global__ void __launch_bounds__(256) k_out(float* __restrict__ out) {
    const int i = blockIdx.x * 256 + threadIdx.x;   // 0 .. 2M-1
    const int c = i & 127;
    float v = g_pool[i];
    out[(size_t)BB*SS*3 + i] = fmaxf(0.f, fmaf(v, g_bnA[2][c], g_bnB[2][c]));
}

// ---------------- launch ----------------
extern "C" void kernel_launch(void* const* d_in, const int* in_sizes, int n_in,
                              void* d_out, int out_size) {
    const float* xyz = (const float*)d_in[0];
    const float* pts = (const float*)d_in[1];
    const float* W0  = (const float*)d_in[2];
    const float* g0  = (const float*)d_in[3];
    const float* b0  = (const float*)d_in[4];
    const float* W1  = (const float*)d_in[5];
    const float* g1  = (const float*)d_in[6];
    const float* b1  = (const float*)d_in[7];
    const float* W2  = (const float*)d_in[8];
    const float* g2  = (const float*)d_in[9];
    const float* b2  = (const float*)d_in[10];
    float* out = (float*)d_out;

    cudaFuncSetAttribute(k_fps,   cudaFuncAttributeMaxDynamicSharedMemorySize, 65536);
    cudaFuncSetAttribute(k_knn,   cudaFuncAttributeMaxDynamicSharedMemorySize, 65536);
    cudaFuncSetAttribute(k_gemm0, cudaFuncAttributeMaxDynamicSharedMemorySize, 51456);
    cudaFuncSetAttribute(k_gemm1, cudaFuncAttributeMaxDynamicSharedMemorySize, 49664);
    cudaFuncSetAttribute(k_gemm2, cudaFuncAttributeMaxDynamicSharedMemorySize, 66048);

    // two padders so k_knn is launch #4 (the one ncu captures)
    k_zero<<<1, 128>>>();
    k_zero<<<1, 128>>>();
    k_fps<<<BB, 1024, 65536>>>(xyz, out);
    k_knn<<<(BB*SS)/16, 512, 65536>>>(xyz);
    k_gemm0<<<MM/128, 256, 51456>>>(xyz, pts, W0);
    k_finalize<<<1, 128>>>(0, 64, g0, b0);
    k_gemm1<<<MM/128, 256, 49664>>>(W1);
    k_finalize<<<1, 128>>>(1, 64, g1, b1);
    k_gemm2<<<MM/128, 256, 66048>>>(W2);
    k_finalize<<<1, 128>>>(2, 128, g2, b2);
    k_out<<<(BB*SS*C2)/256, 256>>>(out);
}

// round 15
// speedup vs baseline: 1.0154x; 1.0149x over previous
#include <cuda_runtime.h>
#include <math.h>

#define BB   16
#define NN   4096
#define SS   1024
#define KK   32
#define CPTS 64
#define CIN  67
#define C0   64
#define C1   64
#define C2   128
#define MM   (BB*SS*KK)      /* 524288 samples */
#define BNEPS 1e-5f
#define FULL 0xffffffffu

// ---------------- scratch (static device memory; no allocations) ----------------
__device__ int    g_fps[BB*SS];
__device__ float  g_new[BB*SS*3];
__device__ int    g_knn[BB*SS*KK];
__device__ float  g_x0[(size_t)MM*C0];
__device__ float  g_x1[(size_t)MM*C1];
__device__ float  g_pool[(size_t)BB*SS*C2];          // pooled (pre-BN) maxima
__device__ float  g_sum[3][128];
__device__ float  g_sq[3][128];
__device__ float  g_bnA[3][128];
__device__ float  g_bnB[3][128];

// ---------------- helpers: exact-order fp32 (no FMA contraction) ----------------
__device__ __forceinline__ float sq3(float a, float b, float c) {
    return __fadd_rn(__fadd_rn(__fmul_rn(a,a), __fmul_rn(b,b)), __fmul_rn(c,c));
}
__device__ __forceinline__ float dot3(float ax,float ay,float az,float bx,float by,float bz) {
    return __fadd_rn(__fadd_rn(__fmul_rn(ax,bx), __fmul_rn(ay,by)), __fmul_rn(az,bz));
}
// packed f32x2 (per-lane IEEE rn: bit-identical to scalar __fadd_rn/__fmul_rn/fmaf)
__device__ __forceinline__ unsigned long long f2pk(float lo, float hi) {
    unsigned long long r; asm("mov.b64 %0, {%1, %2};" : "=l"(r) : "f"(lo), "f"(hi)); return r;
}
__device__ __forceinline__ void f2up(unsigned long long v, float& lo, float& hi) {
    asm("mov.b64 {%0, %1}, %2;" : "=f"(lo), "=f"(hi) : "l"(v));
}
__device__ __forceinline__ unsigned long long f2add(unsigned long long a, unsigned long long b) {
    unsigned long long r; asm("add.rn.f32x2 %0, %1, %2;" : "=l"(r) : "l"(a), "l"(b)); return r;
}
__device__ __forceinline__ unsigned long long f2mul(unsigned long long a, unsigned long long b) {
    unsigned long long r; asm("mul.rn.f32x2 %0, %1, %2;" : "=l"(r) : "l"(a), "l"(b)); return r;
}
__device__ __forceinline__ unsigned long long f2fma(unsigned long long a, unsigned long long b,
                                                   unsigned long long c) {
    unsigned long long r; asm("fma.rn.f32x2 %0, %1, %2, %3;" : "=l"(r) : "l"(a), "l"(b), "l"(c)); return r;
}
// monotone float -> uint (total order, handles negatives from rounding)
__device__ __forceinline__ unsigned int ordf(float f) {
    unsigned int b = __float_as_uint(f);
    return (b & 0x80000000u) ? ~b : (b | 0x80000000u);
}

// ---------------- zero BN stats (must run every launch: graph replays) ----------
__global__ void k_zero() {
    int t = threadIdx.x;
    if (t < 128) {
        #pragma unroll
        for (int l = 0; l < 3; l++) { g_sum[l][t] = 0.f; g_sq[l][t] = 0.f; }
    }
}

// ---------------- FPS: 1 block (1024 thr) per batch, points in registers -------
// Points stored NEGATED: dx = (-x) + cp.x = -(x - cp.x); square identical bits.
// Saves the per-iteration centroid negations.
__global__ void __launch_bounds__(1024) k_fps(const float* __restrict__ xyz,
                                              float* __restrict__ out) {
    extern __shared__ float4 fps_pts[];   // 4096 float4 = 64KB (centroid lookup)
    __shared__ unsigned long long skey[3];
    const int b = blockIdx.x, tid = threadIdx.x;
    const float* base = xyz + (size_t)b * NN * 3;
    for (int i = tid; i < NN; i += 1024) {
        float x = base[i*3], y = base[i*3+1], z = base[i*3+2];
        fps_pts[i] = make_float4(x, y, z, 0.f);
    }
    if (tid < 3) skey[tid] = 0ull;
    __syncthreads();

    float4 p0 = fps_pts[tid], p1 = fps_pts[tid+1024];
    float4 p2 = fps_pts[tid+2048], p3 = fps_pts[tid+3072];
    unsigned long long xA = f2pk(-p0.x, -p1.x), yA = f2pk(-p0.y, -p1.y), zA = f2pk(-p0.z, -p1.z);
    unsigned long long xB = f2pk(-p2.x, -p3.x), yB = f2pk(-p2.y, -p3.y), zB = f2pk(-p2.z, -p3.z);

    float dist0 = INFINITY, dist1 = INFINITY, dist2 = INFINITY, dist3 = INFINITY;

    int far = 0;
    int s0 = 0;                                  // it % 3
    for (int it = 0; it < SS; it++) {
        int s1 = s0 + 1; if (s1 == 3) s1 = 0;    // (it+1) % 3
        float4 cp = fps_pts[far];                // uniform -> LDS broadcast
        if (tid == 0) {
            skey[s1] = 0ull;                     // reset slot for NEXT iter
            g_fps[b*SS + it] = far;
            int o = (b*SS + it) * 3;
            g_new[o]   = cp.x; g_new[o+1] = cp.y; g_new[o+2] = cp.z;
            out[o]     = cp.x; out[o+1]   = cp.y; out[o+2]   = cp.z;
        }
        unsigned long long cx2 = f2pk(cp.x, cp.x);
        unsigned long long cy2 = f2pk(cp.y, cp.y);
        unsigned long long cz2 = f2pk(cp.z, cp.z);
        {   // pair A: ((dx*dx + dy*dy) + dz*dz), strict order per lane
            unsigned long long dx = f2add(xA, cx2), dy = f2add(yA, cy2), dz = f2add(zA, cz2);
            unsigned long long s = f2add(f2add(f2mul(dx,dx), f2mul(dy,dy)), f2mul(dz,dz));
            float d0, d1; f2up(s, d0, d1);
            dist0 = fminf(dist0, d0); dist1 = fminf(dist1, d1);
        }
        {   // pair B
            unsigned long long dx = f2add(xB, cx2), dy = f2add(yB, cy2), dz = f2add(zB, cz2);
            unsigned long long s = f2add(f2add(f2mul(dx,dx), f2mul(dy,dy)), f2mul(dz,dz));
            float d2, d3; f2up(s, d2, d3);
            dist2 = fminf(dist2, d2); dist3 = fminf(dist3, d3);
        }
        float bd = fmaxf(fmaxf(dist0, dist1), fmaxf(dist2, dist3));
        int bi = (dist0 == bd) ? tid
               : (dist1 == bd) ? tid + 1024
               : (dist2 == bd) ? tid + 2048
               :                 tid + 3072;      // ascending index => lowest on tie

        unsigned int db   = __float_as_uint(bd);  // bd >= 0 -> order-preserving bits
        unsigned int wmax = __reduce_max_sync(FULL, db);
        unsigned int cand = (db == wmax) ? (unsigned int)bi : 0xffffffffu;
        unsigned int wbi  = __reduce_min_sync(FULL, cand);
        if ((tid & 31) == 0) {
            unsigned long long key =
                ((unsigned long long)wmax << 32) |
                (unsigned long long)(NN - 1u - wbi);
            atomicMax(&skey[s0], key);
        }
        __syncthreads();
        far = NN - 1 - (int)((unsigned int)(skey[s0] & 0xffffffffull));
        s0 = s1;
    }
}

// ---------------- KNN: warp-cooperative streaming top-32 ----------------
__global__ void __launch_bounds__(512) k_knn(const float* __restrict__ xyz) {
    extern __shared__ float4 sp[];        // 4096 float4 = 64KB
    const int tid  = threadIdx.x;
    const int lane = tid & 31;
    const int w    = tid >> 5;                   // 16 warps = 16 queries/block
    const int b    = blockIdx.x >> 6;            // 64 blocks per batch
    const int s    = (blockIdx.x & 63) * 16 + w;
    const int q    = b * SS + s;

    const float* base = xyz + (size_t)b * NN * 3;
    for (int i = tid; i < NN; i += 512) {
        float x = base[i*3], y = base[i*3+1], z = base[i*3+2];
        sp[i] = make_float4(x, y, z, sq3(x, y, z));
    }
    __syncthreads();

    const int qo = q * 3;
    const float qx = g_new[qo], qy = g_new[qo+1], qz = g_new[qo+2];
    const float qs2 = sq3(qx, qy, qz);

    unsigned int ru; int ri;
    {
        float4 p = sp[lane];
        float t = dot3(qx,qy,qz, p.x,p.y,p.z);
        float d = __fadd_rn(__fadd_rn(qs2, -2.0f*t), p.w);
        ru = ordf(d); ri = lane;
    }
    unsigned int cmu = __reduce_max_sync(FULL, ru);

    for (int j0 = KK; j0 < NN; j0 += 32) {
        float4 p = sp[j0 + lane];
        float t = dot3(qx,qy,qz, p.x,p.y,p.z);
        float d = __fadd_rn(__fadd_rn(qs2, -2.0f*t), p.w);
        unsigned int uu = ordf(d);
        unsigned int mask = __ballot_sync(FULL, uu < cmu);
        while (mask) {                            // warp-uniform loop
            int src = __ffs(mask) - 1;
            unsigned int du = __shfl_sync(FULL, uu, src);
            int di = j0 + src;
            unsigned int hb = __ballot_sync(FULL, ru == cmu);
            int holder = __ffs(hb) - 1;           // evict one instance of current max
            if (lane == holder) { ru = du; ri = di; }
            if (lane == src) uu = 0xffffffffu;    // consumed
            cmu = __reduce_max_sync(FULL, ru);
            mask = __ballot_sync(FULL, uu < cmu);
        }
    }
    g_knn[(size_t)q * KK + lane] = ri;
}

// ---------------- layer 0: gather(67) + GEMM(67->64, FFMA2) + stats ----------
__global__ void __launch_bounds__(256) k_gemm0(const float* __restrict__ xyz,
                                               const float* __restrict__ pts,
                                               const float* __restrict__ W0) {
    extern __shared__ float sm0[];
    float* featT = sm0;               // [67][128]
    float* ws    = sm0 + CIN*128;     // [67][64]
    const int tid = threadIdx.x;
    const int m0 = blockIdx.x * 128;
    const int b = m0 >> 15;           // 32768 samples per batch
    const int s_base = (m0 & 32767) >> 5;

    { // gather: 2 threads per sample
        const int ms = tid >> 1, h = tid & 1;
        const int s = s_base + (ms >> 5);
        const int k = ms & 31;
        const int idx = g_knn[(b*SS + s)*KK + k];
        if (h == 0) {
            int qo = (b*SS + s)*3, po = (b*NN + idx)*3;
            featT[0*128 + ms] = __fadd_rn(xyz[po],   -g_new[qo]);
            featT[1*128 + ms] = __fadd_rn(xyz[po+1], -g_new[qo+1]);
            featT[2*128 + ms] = __fadd_rn(xyz[po+2], -g_new[qo+2]);
        }
        const float4* p4 = (const float4*)(pts + ((size_t)(b*NN + idx)) * CPTS);
        #pragma unroll
        for (int q = 0; q < 8; q++) {
            float4 v = p4[h*8 + q];
            int c = 3 + h*32 + q*4;
            featT[(c+0)*128 + ms] = v.x;
            featT[(c+1)*128 + ms] = v.y;
            featT[(c+2)*128 + ms] = v.z;
            featT[(c+3)*128 + ms] = v.w;
        }
    }
    for (int i = tid; i < CIN*64; i += 256) {
        int c = i >> 6, o = i & 63;
        ws[i] = W0[o*CIN + c];
    }
    __syncthreads();

    const int to = tid & 15, ts = tid >> 4;
    const int o4 = to*4, s8 = ts*8;
    unsigned long long accp[4][4];
    #pragma unroll
    for (int p = 0; p < 4; p++)
        #pragma unroll
        for (int j = 0; j < 4; j++) accp[p][j] = 0ull;

    #pragma unroll 4
    for (int c = 0; c < CIN; c++) {
        float4 wv = *(const float4*)(ws + c*64 + o4);
        unsigned long long w0 = f2pk(wv.x, wv.x), w1 = f2pk(wv.y, wv.y);
        unsigned long long w2 = f2pk(wv.z, wv.z), w3 = f2pk(wv.w, wv.w);
        ulonglong2 fA = *(const ulonglong2*)(featT + c*128 + s8);
        ulonglong2 fB = *(const ulonglong2*)(featT + c*128 + s8 + 4);
        unsigned long long f[4] = {fA.x, fA.y, fB.x, fB.y};
        #pragma unroll
        for (int p = 0; p < 4; p++) {
            accp[p][0] = f2fma(f[p], w0, accp[p][0]);
            accp[p][1] = f2fma(f[p], w1, accp[p][1]);
            accp[p][2] = f2fma(f[p], w2, accp[p][2]);
            accp[p][3] = f2fma(f[p], w3, accp[p][3]);
        }
    }
    float acc[8][4];
    #pragma unroll
    for (int p = 0; p < 4; p++)
        #pragma unroll
        for (int j = 0; j < 4; j++) f2up(accp[p][j], acc[2*p][j], acc[2*p+1][j]);

    #pragma unroll
    for (int i = 0; i < 8; i++)
        *(float4*)(g_x0 + (size_t)(m0 + s8 + i)*C0 + o4) =
            make_float4(acc[i][0], acc[i][1], acc[i][2], acc[i][3]);

    float ls[4], lq[4];
    #pragma unroll
    for (int j = 0; j < 4; j++) {
        float s = 0.f, q = 0.f;
        #pragma unroll
        for (int i = 0; i < 8; i++) { float v = acc[i][j]; s += v; q = fmaf(v, v, q); }
        ls[j] = s; lq[j] = q;
    }
    __syncthreads();
    float* redS = sm0;  float* redQ = sm0 + 1024;
    #pragma unroll
    for (int j = 0; j < 4; j++) { redS[ts*64 + o4 + j] = ls[j]; redQ[ts*64 + o4 + j] = lq[j]; }
    __syncthreads();
    if (tid < 64) {
        float s = 0.f, q = 0.f;
        #pragma unroll
        for (int t2 = 0; t2 < 16; t2++) { s += redS[t2*64 + tid]; q += redQ[t2*64 + tid]; }
        atomicAdd(&g_sum[0][tid], s);
        atomicAdd(&g_sq[0][tid],  q);
    }
}

// ---------------- BN finalize ----------------
__global__ void k_finalize(int l, int cout,
                           const float* __restrict__ gamma,
                           const float* __restrict__ beta) {
    int t = threadIdx.x;
    if (t < cout) {
        const float inv = 1.f / (float)MM;
        float mean = g_sum[l][t] * inv;
        float var  = g_sq[l][t] * inv - mean*mean;
        float sc   = gamma[t] * rsqrtf(var + BNEPS);
        g_bnA[l][t] = sc;
        g_bnB[l][t] = fmaf(-mean, sc, beta[t]);
    }
}

// ---------------- layer 1: BN0+ReLU load + GEMM(64->64, FFMA2) + stats --------
__global__ void __launch_bounds__(256) k_gemm1(const float* __restrict__ W1) {
    extern __shared__ float sm1[];
    float* featT = sm1;             // [64][128]
    float* ws    = sm1 + 64*128;    // [64][64]
    float* sA    = ws + 64*64;
    float* sB    = sA + 64;
    const int tid = threadIdx.x;
    if (tid < 64) { sA[tid] = g_bnA[0][tid]; sB[tid] = g_bnB[0][tid]; }
    __syncthreads();
    const int m0 = blockIdx.x * 128;
    {
        const int ms = tid >> 1, h = tid & 1;
        const float4* row = (const float4*)(g_x0 + (size_t)(m0 + ms) * 64);
        #pragma unroll
        for (int q = 0; q < 8; q++) {
            float4 v = row[h*8 + q];
            int c = h*32 + q*4;
            featT[(c+0)*128 + ms] = fmaxf(0.f, fmaf(v.x, sA[c+0], sB[c+0]));
            featT[(c+1)*128 + ms] = fmaxf(0.f, fmaf(v.y, sA[c+1], sB[c+1]));
            featT[(c+2)*128 + ms] = fmaxf(0.f, fmaf(v.z, sA[c+2], sB[c+2]));
            featT[(c+3)*128 + ms] = fmaxf(0.f, fmaf(v.w, sA[c+3], sB[c+3]));
        }
    }
    for (int i = tid; i < 64*64; i += 256) {
        int c = i >> 6, o = i & 63;
        ws[i] = W1[o*64 + c];
    }
    __syncthreads();

    const int to = tid & 15, ts = tid >> 4;
    const int o4 = to*4, s8 = ts*8;
    unsigned long long accp[4][4];
    #pragma unroll
    for (int p = 0; p < 4; p++)
        #pragma unroll
        for (int j = 0; j < 4; j++) accp[p][j] = 0ull;

    #pragma unroll 4
    for (int c = 0; c < 64; c++) {
        float4 wv = *(const float4*)(ws + c*64 + o4);
        unsigned long long w0 = f2pk(wv.x, wv.x), w1 = f2pk(wv.y, wv.y);
        unsigned long long w2 = f2pk(wv.z, wv.z), w3 = f2pk(wv.w, wv.w);
        ulonglong2 fA = *(const ulonglong2*)(featT + c*128 + s8);
        ulonglong2 fB = *(const ulonglong2*)(featT + c*128 + s8 + 4);
        unsigned long long f[4] = {fA.x, fA.y, fB.x, fB.y};
        #pragma unroll
        for (int p = 0; p < 4; p++) {
            accp[p][0] = f2fma(f[p], w0, accp[p][0]);
            accp[p][1] = f2fma(f[p], w1, accp[p][1]);
            accp[p][2] = f2fma(f[p], w2, accp[p][2]);
            accp[p][3] = f2fma(f[p], w3, accp[p][3]);
        }
    }
    float acc[8][4];
    #pragma unroll
    for (int p = 0; p < 4; p++)
        #pragma unroll
        for (int j = 0; j < 4; j++) f2up(accp[p][j], acc[2*p][j], acc[2*p+1][j]);

    #pragma unroll
    for (int i = 0; i < 8; i++)
        *(float4*)(g_x1 + (size_t)(m0 + s8 + i)*C1 + o4) =
            make_float4(acc[i][0], acc[i][1], acc[i][2], acc[i][3]);

    float ls[4], lq[4];
    #pragma unroll
    for (int j = 0; j < 4; j++) {
        float s = 0.f, q = 0.f;
        #pragma unroll
        for (int i = 0; i < 8; i++) { float v = acc[i][j]; s += v; q = fmaf(v, v, q); }
        ls[j] = s; lq[j] = q;
    }
    __syncthreads();
    float* redS = sm1;  float* redQ = sm1 + 1024;
    #pragma unroll
    for (int j = 0; j < 4; j++) { redS[ts*64 + o4 + j] = ls[j]; redQ[ts*64 + o4 + j] = lq[j]; }
    __syncthreads();
    if (tid < 64) {
        float s = 0.f, q = 0.f;
        #pragma unroll
        for (int t2 = 0; t2 < 16; t2++) { s += redS[t2*64 + tid]; q += redQ[t2*64 + tid]; }
        atomicAdd(&g_sum[1][tid], s);
        atomicAdd(&g_sq[1][tid],  q);
    }
}

// ---------------- layer 2: BN1+ReLU load + GEMM(64->128, FFMA2) + stats + pool -
__global__ void __launch_bounds__(256) k_gemm2(const float* __restrict__ W2) {
    extern __shared__ float sm2[];
    float* featT = sm2;             // [64][128]
    float* ws    = sm2 + 64*128;    // [64][128]
    float* sA    = ws + 64*128;
    float* sB    = sA + 64;
    const int tid = threadIdx.x;
    if (tid < 64) { sA[tid] = g_bnA[1][tid]; sB[tid] = g_bnB[1][tid]; }
    __syncthreads();
    const int m0 = blockIdx.x * 128;
    {
        const int ms = tid >> 1, h = tid & 1;
        const float4* row = (const float4*)(g_x1 + (size_t)(m0 + ms) * 64);
        #pragma unroll
        for (int q = 0; q < 8; q++) {
            float4 v = row[h*8 + q];
            int c = h*32 + q*4;
            featT[(c+0)*128 + ms] = fmaxf(0.f, fmaf(v.x, sA[c+0], sB[c+0]));
            featT[(c+1)*128 + ms] = fmaxf(0.f, fmaf(v.y, sA[c+1], sB[c+1]));
            featT[(c+2)*128 + ms] = fmaxf(0.f, fmaf(v.z, sA[c+2], sB[c+2]));
            featT[(c+3)*128 + ms] = fmaxf(0.f, fmaf(v.w, sA[c+3], sB[c+3]));
        }
    }
    for (int i = tid; i < 64*128; i += 256) {
        int c = i >> 7, o = i & 127;
        ws[i] = W2[o*64 + c];
    }
    __syncthreads();

    const int to = tid & 31, ts = tid >> 5;      // 32 ch-groups x 8 sample-groups
    const int o4 = to*4, s16 = ts*16;
    unsigned long long accp[8][4];
    #pragma unroll
    for (int p = 0; p < 8; p++)
        #pragma unroll
        for (int j = 0; j < 4; j++) accp[p][j] = 0ull;

    #pragma unroll 2
    for (int c = 0; c < 64; c++) {
        float4 wv = *(const float4*)(ws + c*128 + o4);
        unsigned long long w0 = f2pk(wv.x, wv.x), w1 = f2pk(wv.y, wv.y);
        unsigned long long w2 = f2pk(wv.z, wv.z), w3 = f2pk(wv.w, wv.w);
        unsigned long long f[8];
        #pragma unroll
        for (int r = 0; r < 4; r++) {
            ulonglong2 fv = *(const ulonglong2*)(featT + c*128 + s16 + r*4);
            f[2*r] = fv.x; f[2*r+1] = fv.y;
        }
        #pragma unroll
        for (int p = 0; p < 8; p++) {
            accp[p][0] = f2fma(f[p], w0, accp[p][0]);
            accp[p][1] = f2fma(f[p], w1, accp[p][1]);
            accp[p][2] = f2fma(f[p], w2, accp[p][2]);
            accp[p][3] = f2fma(f[p], w3, accp[p][3]);
        }
    }
    float acc[16][4];
    #pragma unroll
    for (int p = 0; p < 8; p++)
        #pragma unroll
        for (int j = 0; j < 4; j++) f2up(accp[p][j], acc[2*p][j], acc[2*p+1][j]);

    // ---- in-block maxpool over k: block owns 4 whole queries (128 samples) ----
    float pm[4];
    #pragma unroll
    for (int j = 0; j < 4; j++) {
        float m = acc[0][j];
        #pragma unroll
        for (int i = 1; i < 16; i++) m = fmaxf(m, acc[i][j]);
        pm[j] = m;
    }
    __syncthreads();                      // featT reads done; reuse smem
    float* poolS = sm2;                   // [8][128]
    #pragma unroll
    for (int j = 0; j < 4; j++) poolS[ts*128 + o4 + j] = pm[j];
    __syncthreads();
    {
        const int ql = tid >> 7;          // 0..1 (covers 2 of 4 with stride)
        const int c  = tid & 127;
        #pragma unroll
        for (int r = 0; r < 2; r++) {
            int qq = ql + r*2;            // 0..3
            float v = fmaxf(poolS[(2*qq)*128 + c], poolS[(2*qq+1)*128 + c]);
            g_pool[(size_t)((m0 >> 5) + qq) * C2 + c] = v;
        }
    }

    // ---- BN2 stats (over all pre-BN samples) ----
    float ls[4], lq[4];
    #pragma unroll
    for (int j = 0; j < 4; j++) {
        float s = 0.f, q = 0.f;
        #pragma unroll
        for (int i = 0; i < 16; i++) { float v = acc[i][j]; s += v; q = fmaf(v, v, q); }
        ls[j] = s; lq[j] = q;
    }
    __syncthreads();
    float* redS = sm2;  float* redQ = sm2 + 1024;
    #pragma unroll
    for (int j = 0; j < 4; j++) { redS[ts*128 + o4 + j] = ls[j]; redQ[ts*128 + o4 + j] = lq[j]; }
    __syncthreads();
    if (tid < 128) {
        float s = 0.f, q = 0.f;
        #pragma unroll
        for (int t2 = 0; t2 < 8; t2++) { s += redS[t2*128 + tid]; q += redQ[t2*128 + tid]; }
        atomicAdd(&g_sum[2][tid], s);
        atomicAdd(&g_sq[2][tid],  q);
    }
}

// ---------------- epilogue: BN2 + ReLU on pooled maxima ----------------
__global__ void __launch_bounds__(256) k_out(float* __restrict__ out) {
    const int i = blockIdx.x * 256 + threadIdx.x;   // 0 .. 2M-1
    const int c = i & 127;
    float v = g_pool[i];
    out[(size_t)BB*SS*3 + i] = fmaxf(0.f, fmaf(v, g_bnA[2][c], g_bnB[2][c]));
}

// ---------------- launch ----------------
extern "C" void kernel_launch(void* const* d_in, const int* in_sizes, int n_in,
                              void* d_out, int out_size) {
    const float* xyz = (const float*)d_in[0];
    const float* pts = (const float*)d_in[1];
    const float* W0  = (const float*)d_in[2];
    const float* g0  = (const float*)d_in[3];
    const float* b0  = (const float*)d_in[4];
    const float* W1  = (const float*)d_in[5];
    const float* g1  = (const float*)d_in[6];
    const float* b1  = (const float*)d_in[7];
    const float* W2  = (const float*)d_in[8];
    const float* g2  = (const float*)d_in[9];
    const float* b2  = (const float*)d_in[10];
    float* out = (float*)d_out;

    cudaFuncSetAttribute(k_fps,   cudaFuncAttributeMaxDynamicSharedMemorySize, 65536);
    cudaFuncSetAttribute(k_knn,   cudaFuncAttributeMaxDynamicSharedMemorySize, 65536);
    cudaFuncSetAttribute(k_gemm0, cudaFuncAttributeMaxDynamicSharedMemorySize, 51456);
    cudaFuncSetAttribute(k_gemm1, cudaFuncAttributeMaxDynamicSharedMemorySize, 49664);
    cudaFuncSetAttribute(k_gemm2, cudaFuncAttributeMaxDynamicSharedMemorySize, 66048);

    // launch #4 (1-based) is the profiled one -> k_gemm0 this round
    k_zero<<<1, 128>>>();
    k_fps<<<BB, 1024, 65536>>>(xyz, out);
    k_knn<<<(BB*SS)/16, 512, 65536>>>(xyz);
    k_gemm0<<<MM/128, 256, 51456>>>(xyz, pts, W0);
    k_finalize<<<1, 128>>>(0, 64, g0, b0);
    k_gemm1<<<MM/128, 256, 49664>>>(W1);
    k_finalize<<<1, 128>>>(1, 64, g1, b1);
    k_gemm2<<<MM/128, 256, 66048>>>(W2);
    k_finalize<<<1, 128>>>(2, 128, g2, b2);
    k_out<<<(BB*SS*C2)/256, 256>>>(out);
}

// round 16
// speedup vs baseline: 1.0859x; 1.0694x over previous
#include <cuda_runtime.h>
#include <math.h>

#define BB   16
#define NN   4096
#define SS   1024
#define KK   32
#define CPTS 64
#define CIN  67
#define C0   64
#define C1   64
#define C2   128
#define MM   (BB*SS*KK)      /* 524288 samples */
#define BNEPS 1e-5f
#define FULL 0xffffffffu

// ---------------- scratch (static device memory; no allocations) ----------------
__device__ int    g_fps[BB*SS];
__device__ float  g_new[BB*SS*3];
__device__ int    g_knn[BB*SS*KK];
__device__ float  g_x0[(size_t)MM*C0];
__device__ float  g_x1[(size_t)MM*C1];
__device__ float  g_pool[(size_t)BB*SS*C2];          // pooled (pre-BN) maxima
__device__ float  g_sum[3][128];
__device__ float  g_sq[3][128];
__device__ float  g_bnA[3][128];
__device__ float  g_bnB[3][128];

// ---------------- helpers: exact-order fp32 (no FMA contraction) ----------------
__device__ __forceinline__ float sq3(float a, float b, float c) {
    return __fadd_rn(__fadd_rn(__fmul_rn(a,a), __fmul_rn(b,b)), __fmul_rn(c,c));
}
__device__ __forceinline__ float dot3(float ax,float ay,float az,float bx,float by,float bz) {
    return __fadd_rn(__fadd_rn(__fmul_rn(ax,bx), __fmul_rn(ay,by)), __fmul_rn(az,bz));
}
// packed f32x2 (per-lane IEEE rn: bit-identical to scalar __fadd_rn/__fmul_rn/fmaf)
__device__ __forceinline__ unsigned long long f2pk(float lo, float hi) {
    unsigned long long r; asm("mov.b64 %0, {%1, %2};" : "=l"(r) : "f"(lo), "f"(hi)); return r;
}
__device__ __forceinline__ void f2up(unsigned long long v, float& lo, float& hi) {
    asm("mov.b64 {%0, %1}, %2;" : "=f"(lo), "=f"(hi) : "l"(v));
}
__device__ __forceinline__ unsigned long long f2add(unsigned long long a, unsigned long long b) {
    unsigned long long r; asm("add.rn.f32x2 %0, %1, %2;" : "=l"(r) : "l"(a), "l"(b)); return r;
}
__device__ __forceinline__ unsigned long long f2mul(unsigned long long a, unsigned long long b) {
    unsigned long long r; asm("mul.rn.f32x2 %0, %1, %2;" : "=l"(r) : "l"(a), "l"(b)); return r;
}
__device__ __forceinline__ unsigned long long f2fma(unsigned long long a, unsigned long long b,
                                                   unsigned long long c) {
    unsigned long long r; asm("fma.rn.f32x2 %0, %1, %2, %3;" : "=l"(r) : "l"(a), "l"(b), "l"(c)); return r;
}
// monotone float -> uint (total order, handles negatives from rounding)
__device__ __forceinline__ unsigned int ordf(float f) {
    unsigned int b = __float_as_uint(f);
    return (b & 0x80000000u) ? ~b : (b | 0x80000000u);
}

// ---------------- zero BN stats (must run every launch: graph replays) ----------
__global__ void k_zero() {
    int t = threadIdx.x;
    if (t < 128) {
        #pragma unroll
        for (int l = 0; l < 3; l++) { g_sum[l][t] = 0.f; g_sq[l][t] = 0.f; }
    }
}

// ---------------- FPS: 1 block (256 thr) per batch, 16 pts/thread in registers --
// Fewer warps => selection/redux overhead paid 8x not 32x per SM; distance math
// unchanged (packed f32x2, per-lane IEEE rn, points negated at init).
__global__ void __launch_bounds__(256) k_fps(const float* __restrict__ xyz,
                                             float* __restrict__ out) {
    extern __shared__ float4 fps_pts[];   // 4096 float4 = 64KB (centroid lookup)
    __shared__ unsigned long long skey[3];
    const int b = blockIdx.x, tid = threadIdx.x;
    const float* base = xyz + (size_t)b * NN * 3;
    for (int i = tid; i < NN; i += 256) {
        float x = base[i*3], y = base[i*3+1], z = base[i*3+2];
        fps_pts[i] = make_float4(x, y, z, 0.f);
    }
    if (tid < 3) skey[tid] = 0ull;
    __syncthreads();

    // point j (0..15) of this thread = global index tid + j*256 (negated coords)
    unsigned long long px[8], py[8], pz[8];
    #pragma unroll
    for (int p = 0; p < 8; p++) {
        float4 a = fps_pts[tid + (2*p)*256];
        float4 c = fps_pts[tid + (2*p+1)*256];
        px[p] = f2pk(-a.x, -c.x); py[p] = f2pk(-a.y, -c.y); pz[p] = f2pk(-a.z, -c.z);
    }
    float dist[16];
    #pragma unroll
    for (int j = 0; j < 16; j++) dist[j] = INFINITY;

    int far = 0;
    int s0 = 0;                                  // it % 3
    for (int it = 0; it < SS; it++) {
        int s1 = s0 + 1; if (s1 == 3) s1 = 0;    // (it+1) % 3
        float4 cp = fps_pts[far];                // uniform -> LDS broadcast
        if (tid == 0) {
            skey[s1] = 0ull;                     // reset slot for NEXT iter
            g_fps[b*SS + it] = far;
            int o = (b*SS + it) * 3;
            g_new[o]   = cp.x; g_new[o+1] = cp.y; g_new[o+2] = cp.z;
            out[o]     = cp.x; out[o+1]   = cp.y; out[o+2]   = cp.z;
        }
        unsigned long long cx2 = f2pk(cp.x, cp.x);
        unsigned long long cy2 = f2pk(cp.y, cp.y);
        unsigned long long cz2 = f2pk(cp.z, cp.z);
        #pragma unroll
        for (int p = 0; p < 8; p++) {
            unsigned long long dx = f2add(px[p], cx2);
            unsigned long long dy = f2add(py[p], cy2);
            unsigned long long dz = f2add(pz[p], cz2);
            unsigned long long s = f2add(f2add(f2mul(dx,dx), f2mul(dy,dy)), f2mul(dz,dz));
            float lo, hi; f2up(s, lo, hi);
            dist[2*p]   = fminf(dist[2*p],   lo);
            dist[2*p+1] = fminf(dist[2*p+1], hi);
        }
        // explicit max tree (value only)
        float m8[8];
        #pragma unroll
        for (int p = 0; p < 8; p++) m8[p] = fmaxf(dist[2*p], dist[2*p+1]);
        float t0 = fmaxf(m8[0], m8[1]), t1 = fmaxf(m8[2], m8[3]);
        float t2 = fmaxf(m8[4], m8[5]), t3 = fmaxf(m8[6], m8[7]);
        float bd = fmaxf(fmaxf(t0, t1), fmaxf(t2, t3));
        // lowest j with dist[j]==bd  (descending overwrite keeps smallest j)
        int jj = 15;
        #pragma unroll
        for (int j = 14; j >= 0; j--) if (dist[j] == bd) jj = j;
        int bi = tid + jj*256;                    // global index; lowest-i tie rule

        unsigned int db   = __float_as_uint(bd);  // bd >= 0 -> order-preserving bits
        unsigned int wmax = __reduce_max_sync(FULL, db);
        unsigned int cand = (db == wmax) ? (unsigned int)bi : 0xffffffffu;
        unsigned int wbi  = __reduce_min_sync(FULL, cand);
        if ((tid & 31) == 0) {
            unsigned long long key =
                ((unsigned long long)wmax << 32) |
                (unsigned long long)(NN - 1u - wbi);
            atomicMax(&skey[s0], key);
        }
        __syncthreads();
        far = NN - 1 - (int)((unsigned int)(skey[s0] & 0xffffffffull));
        s0 = s1;
    }
}

// ---------------- KNN: warp-cooperative streaming top-32 ----------------
__global__ void __launch_bounds__(512) k_knn(const float* __restrict__ xyz) {
    extern __shared__ float4 sp[];        // 4096 float4 = 64KB
    const int tid  = threadIdx.x;
    const int lane = tid & 31;
    const int w    = tid >> 5;                   // 16 warps = 16 queries/block
    const int b    = blockIdx.x >> 6;            // 64 blocks per batch
    const int s    = (blockIdx.x & 63) * 16 + w;
    const int q    = b * SS + s;

    const float* base = xyz + (size_t)b * NN * 3;
    for (int i = tid; i < NN; i += 512) {
        float x = base[i*3], y = base[i*3+1], z = base[i*3+2];
        sp[i] = make_float4(x, y, z, sq3(x, y, z));
    }
    __syncthreads();

    const int qo = q * 3;
    const float qx = g_new[qo], qy = g_new[qo+1], qz = g_new[qo+2];
    const float qs2 = sq3(qx, qy, qz);

    unsigned int ru; int ri;
    {
        float4 p = sp[lane];
        float t = dot3(qx,qy,qz, p.x,p.y,p.z);
        float d = __fadd_rn(__fadd_rn(qs2, -2.0f*t), p.w);
        ru = ordf(d); ri = lane;
    }
    unsigned int cmu = __reduce_max_sync(FULL, ru);

    for (int j0 = KK; j0 < NN; j0 += 32) {
        float4 p = sp[j0 + lane];
        float t = dot3(qx,qy,qz, p.x,p.y,p.z);
        float d = __fadd_rn(__fadd_rn(qs2, -2.0f*t), p.w);
        unsigned int uu = ordf(d);
        unsigned int mask = __ballot_sync(FULL, uu < cmu);
        while (mask) {                            // warp-uniform loop
            int src = __ffs(mask) - 1;
            unsigned int du = __shfl_sync(FULL, uu, src);
            int di = j0 + src;
            unsigned int hb = __ballot_sync(FULL, ru == cmu);
            int holder = __ffs(hb) - 1;           // evict one instance of current max
            if (lane == holder) { ru = du; ri = di; }
            if (lane == src) uu = 0xffffffffu;    // consumed
            cmu = __reduce_max_sync(FULL, ru);
            mask = __ballot_sync(FULL, uu < cmu);
        }
    }
    g_knn[(size_t)q * KK + lane] = ri;
}

// ---------------- layer 0: gather + GEMM(67->64) 8s x 8o FFMA2 + stats ---------
// block = 256 samples (8 whole queries), 256 threads, thread tile 8 samples x 8 out
__global__ void __launch_bounds__(256) k_gemm0(const float* __restrict__ xyz,
                                               const float* __restrict__ pts,
                                               const float* __restrict__ W0) {
    extern __shared__ float sm0[];
    float* featT = sm0;               // [67][256]
    float* ws    = sm0 + CIN*256;     // [67][64]
    const int tid = threadIdx.x;
    const int m0 = blockIdx.x * 256;
    const int b = m0 >> 15;           // 32768 samples per batch
    const int s_base = (m0 & 32767) >> 5;

    { // gather: 1 thread per sample
        const int ms = tid;
        const int s = s_base + (ms >> 5);
        const int k = ms & 31;
        const int idx = g_knn[(b*SS + s)*KK + k];
        int qo = (b*SS + s)*3, po = (b*NN + idx)*3;
        featT[0*256 + ms] = __fadd_rn(xyz[po],   -g_new[qo]);
        featT[1*256 + ms] = __fadd_rn(xyz[po+1], -g_new[qo+1]);
        featT[2*256 + ms] = __fadd_rn(xyz[po+2], -g_new[qo+2]);
        const float4* p4 = (const float4*)(pts + ((size_t)(b*NN + idx)) * CPTS);
        #pragma unroll
        for (int q = 0; q < 16; q++) {
            float4 v = p4[q];
            int c = 3 + q*4;
            featT[(c+0)*256 + ms] = v.x;
            featT[(c+1)*256 + ms] = v.y;
            featT[(c+2)*256 + ms] = v.z;
            featT[(c+3)*256 + ms] = v.w;
        }
    }
    for (int i = tid; i < CIN*64; i += 256) {
        int c = i >> 6, o = i & 63;
        ws[i] = W0[o*CIN + c];
    }
    __syncthreads();

    const int to = tid & 7, ts = tid >> 3;       // 8 out-groups x 32 sample-groups
    const int o8 = to*8, s8 = ts*8;
    unsigned long long accp[4][8];
    #pragma unroll
    for (int p = 0; p < 4; p++)
        #pragma unroll
        for (int j = 0; j < 8; j++) accp[p][j] = 0ull;

    #pragma unroll 4
    for (int c = 0; c < CIN; c++) {
        float4 wv0 = *(const float4*)(ws + c*64 + o8);
        float4 wv1 = *(const float4*)(ws + c*64 + o8 + 4);
        unsigned long long w[8];
        w[0] = f2pk(wv0.x, wv0.x); w[1] = f2pk(wv0.y, wv0.y);
        w[2] = f2pk(wv0.z, wv0.z); w[3] = f2pk(wv0.w, wv0.w);
        w[4] = f2pk(wv1.x, wv1.x); w[5] = f2pk(wv1.y, wv1.y);
        w[6] = f2pk(wv1.z, wv1.z); w[7] = f2pk(wv1.w, wv1.w);
        ulonglong2 fA = *(const ulonglong2*)(featT + c*256 + s8);
        ulonglong2 fB = *(const ulonglong2*)(featT + c*256 + s8 + 4);
        unsigned long long f[4] = {fA.x, fA.y, fB.x, fB.y};
        #pragma unroll
        for (int p = 0; p < 4; p++)
            #pragma unroll
            for (int j = 0; j < 8; j++)
                accp[p][j] = f2fma(f[p], w[j], accp[p][j]);
    }
    float acc[8][8];
    #pragma unroll
    for (int p = 0; p < 4; p++)
        #pragma unroll
        for (int j = 0; j < 8; j++) f2up(accp[p][j], acc[2*p][j], acc[2*p+1][j]);

    #pragma unroll
    for (int i = 0; i < 8; i++) {
        *(float4*)(g_x0 + (size_t)(m0 + s8 + i)*C0 + o8) =
            make_float4(acc[i][0], acc[i][1], acc[i][2], acc[i][3]);
        *(float4*)(g_x0 + (size_t)(m0 + s8 + i)*C0 + o8 + 4) =
            make_float4(acc[i][4], acc[i][5], acc[i][6], acc[i][7]);
    }

    float ls[8], lq[8];
    #pragma unroll
    for (int j = 0; j < 8; j++) {
        float s = 0.f, q = 0.f;
        #pragma unroll
        for (int i = 0; i < 8; i++) { float v = acc[i][j]; s += v; q = fmaf(v, v, q); }
        ls[j] = s; lq[j] = q;
    }
    __syncthreads();
    float* redS = sm0;  float* redQ = sm0 + 2048;
    #pragma unroll
    for (int j = 0; j < 8; j++) { redS[ts*64 + o8 + j] = ls[j]; redQ[ts*64 + o8 + j] = lq[j]; }
    __syncthreads();
    if (tid < 64) {
        float s = 0.f, q = 0.f;
        #pragma unroll
        for (int t2 = 0; t2 < 32; t2++) { s += redS[t2*64 + tid]; q += redQ[t2*64 + tid]; }
        atomicAdd(&g_sum[0][tid], s);
        atomicAdd(&g_sq[0][tid],  q);
    }
}

// ---------------- BN finalize ----------------
__global__ void k_finalize(int l, int cout,
                           const float* __restrict__ gamma,
                           const float* __restrict__ beta) {
    int t = threadIdx.x;
    if (t < cout) {
        const float inv = 1.f / (float)MM;
        float mean = g_sum[l][t] * inv;
        float var  = g_sq[l][t] * inv - mean*mean;
        float sc   = gamma[t] * rsqrtf(var + BNEPS);
        g_bnA[l][t] = sc;
        g_bnB[l][t] = fmaf(-mean, sc, beta[t]);
    }
}

// ---------------- layer 1: BN0+ReLU load + GEMM(64->64) 8s x 8o + stats --------
__global__ void __launch_bounds__(256) k_gemm1(const float* __restrict__ W1) {
    extern __shared__ float sm1[];
    float* featT = sm1;             // [64][256]
    float* ws    = sm1 + 64*256;    // [64][64]
    float* sA    = ws + 64*64;
    float* sB    = sA + 64;
    const int tid = threadIdx.x;
    if (tid < 64) { sA[tid] = g_bnA[0][tid]; sB[tid] = g_bnB[0][tid]; }
    __syncthreads();
    const int m0 = blockIdx.x * 256;
    {   // 1 thread per sample
        const float4* row = (const float4*)(g_x0 + (size_t)(m0 + tid) * 64);
        #pragma unroll
        for (int q = 0; q < 16; q++) {
            float4 v = row[q];
            int c = q*4;
            featT[(c+0)*256 + tid] = fmaxf(0.f, fmaf(v.x, sA[c+0], sB[c+0]));
            featT[(c+1)*256 + tid] = fmaxf(0.f, fmaf(v.y, sA[c+1], sB[c+1]));
            featT[(c+2)*256 + tid] = fmaxf(0.f, fmaf(v.z, sA[c+2], sB[c+2]));
            featT[(c+3)*256 + tid] = fmaxf(0.f, fmaf(v.w, sA[c+3], sB[c+3]));
        }
    }
    for (int i = tid; i < 64*64; i += 256) {
        int c = i >> 6, o = i & 63;
        ws[i] = W1[o*64 + c];
    }
    __syncthreads();

    const int to = tid & 7, ts = tid >> 3;
    const int o8 = to*8, s8 = ts*8;
    unsigned long long accp[4][8];
    #pragma unroll
    for (int p = 0; p < 4; p++)
        #pragma unroll
        for (int j = 0; j < 8; j++) accp[p][j] = 0ull;

    #pragma unroll 4
    for (int c = 0; c < 64; c++) {
        float4 wv0 = *(const float4*)(ws + c*64 + o8);
        float4 wv1 = *(const float4*)(ws + c*64 + o8 + 4);
        unsigned long long w[8];
        w[0] = f2pk(wv0.x, wv0.x); w[1] = f2pk(wv0.y, wv0.y);
        w[2] = f2pk(wv0.z, wv0.z); w[3] = f2pk(wv0.w, wv0.w);
        w[4] = f2pk(wv1.x, wv1.x); w[5] = f2pk(wv1.y, wv1.y);
        w[6] = f2pk(wv1.z, wv1.z); w[7] = f2pk(wv1.w, wv1.w);
        ulonglong2 fA = *(const ulonglong2*)(featT + c*256 + s8);
        ulonglong2 fB = *(const ulonglong2*)(featT + c*256 + s8 + 4);
        unsigned long long f[4] = {fA.x, fA.y, fB.x, fB.y};
        #pragma unroll
        for (int p = 0; p < 4; p++)
            #pragma unroll
            for (int j = 0; j < 8; j++)
                accp[p][j] = f2fma(f[p], w[j], accp[p][j]);
    }
    float acc[8][8];
    #pragma unroll
    for (int p = 0; p < 4; p++)
        #pragma unroll
        for (int j = 0; j < 8; j++) f2up(accp[p][j], acc[2*p][j], acc[2*p+1][j]);

    #pragma unroll
    for (int i = 0; i < 8; i++) {
        *(float4*)(g_x1 + (size_t)(m0 + s8 + i)*C1 + o8) =
            make_float4(acc[i][0], acc[i][1], acc[i][2], acc[i][3]);
        *(float4*)(g_x1 + (size_t)(m0 + s8 + i)*C1 + o8 + 4) =
            make_float4(acc[i][4], acc[i][5], acc[i][6], acc[i][7]);
    }

    float ls[8], lq[8];
    #pragma unroll
    for (int j = 0; j < 8; j++) {
        float s = 0.f, q = 0.f;
        #pragma unroll
        for (int i = 0; i < 8; i++) { float v = acc[i][j]; s += v; q = fmaf(v, v, q); }
        ls[j] = s; lq[j] = q;
    }
    __syncthreads();
    float* redS = sm1;  float* redQ = sm1 + 2048;
    #pragma unroll
    for (int j = 0; j < 8; j++) { redS[ts*64 + o8 + j] = ls[j]; redQ[ts*64 + o8 + j] = lq[j]; }
    __syncthreads();
    if (tid < 64) {
        float s = 0.f, q = 0.f;
        #pragma unroll
        for (int t2 = 0; t2 < 32; t2++) { s += redS[t2*64 + tid]; q += redQ[t2*64 + tid]; }
        atomicAdd(&g_sum[1][tid], s);
        atomicAdd(&g_sq[1][tid],  q);
    }
}

// ---------------- layer 2: BN1+ReLU load + GEMM(64->128) 8s x 8o + stats + pool -
// block = 128 samples (4 whole queries), 256 threads
__global__ void __launch_bounds__(256) k_gemm2(const float* __restrict__ W2) {
    extern __shared__ float sm2[];
    float* featT = sm2;             // [64][128]
    float* ws    = sm2 + 64*128;    // [64][128]
    float* sA    = ws + 64*128;
    float* sB    = sA + 64;
    const int tid = threadIdx.x;
    if (tid < 64) { sA[tid] = g_bnA[1][tid]; sB[tid] = g_bnB[1][tid]; }
    __syncthreads();
    const int m0 = blockIdx.x * 128;
    {
        const int ms = tid >> 1, h = tid & 1;
        const float4* row = (const float4*)(g_x1 + (size_t)(m0 + ms) * 64);
        #pragma unroll
        for (int q = 0; q < 8; q++) {
            float4 v = row[h*8 + q];
            int c = h*32 + q*4;
            featT[(c+0)*128 + ms] = fmaxf(0.f, fmaf(v.x, sA[c+0], sB[c+0]));
            featT[(c+1)*128 + ms] = fmaxf(0.f, fmaf(v.y, sA[c+1], sB[c+1]));
            featT[(c+2)*128 + ms] = fmaxf(0.f, fmaf(v.z, sA[c+2], sB[c+2]));
            featT[(c+3)*128 + ms] = fmaxf(0.f, fmaf(v.w, sA[c+3], sB[c+3]));
        }
    }
    for (int i = tid; i < 64*128; i += 256) {
        int c = i >> 7, o = i & 127;
        ws[i] = W2[o*64 + c];
    }
    __syncthreads();

    const int to = tid & 15, ts = tid >> 4;      // 16 out-groups x 16 sample-groups
    const int o8 = to*8, s8 = ts*8;
    unsigned long long accp[4][8];
    #pragma unroll
    for (int p = 0; p < 4; p++)
        #pragma unroll
        for (int j = 0; j < 8; j++) accp[p][j] = 0ull;

    #pragma unroll 4
    for (int c = 0; c < 64; c++) {
        float4 wv0 = *(const float4*)(ws + c*128 + o8);
        float4 wv1 = *(const float4*)(ws + c*128 + o8 + 4);
        unsigned long long w[8];
        w[0] = f2pk(wv0.x, wv0.x); w[1] = f2pk(wv0.y, wv0.y);
        w[2] = f2pk(wv0.z, wv0.z); w[3] = f2pk(wv0.w, wv0.w);
        w[4] = f2pk(wv1.x, wv1.x); w[5] = f2pk(wv1.y, wv1.y);
        w[6] = f2pk(wv1.z, wv1.z); w[7] = f2pk(wv1.w, wv1.w);
        ulonglong2 fA = *(const ulonglong2*)(featT + c*128 + s8);
        ulonglong2 fB = *(const ulonglong2*)(featT + c*128 + s8 + 4);
        unsigned long long f[4] = {fA.x, fA.y, fB.x, fB.y};
        #pragma unroll
        for (int p = 0; p < 4; p++)
            #pragma unroll
            for (int j = 0; j < 8; j++)
                accp[p][j] = f2fma(f[p], w[j], accp[p][j]);
    }
    float acc[8][8];
    #pragma unroll
    for (int p = 0; p < 4; p++)
        #pragma unroll
        for (int j = 0; j < 8; j++) f2up(accp[p][j], acc[2*p][j], acc[2*p+1][j]);

    // ---- pool over this thread's 8 samples (all within one query: ts*8..ts*8+7) --
    float pm[8];
    #pragma unroll
    for (int j = 0; j < 8; j++) {
        float m = acc[0][j];
        #pragma unroll
        for (int i = 1; i < 8; i++) m = fmaxf(m, acc[i][j]);
        pm[j] = m;
    }
    __syncthreads();                      // featT reads done; reuse smem
    float* poolS = sm2;                   // [16][128]
    #pragma unroll
    for (int j = 0; j < 8; j++) poolS[ts*128 + o8 + j] = pm[j];
    __syncthreads();
    #pragma unroll
    for (int r = 0; r < 2; r++) {
        int idx2 = tid + r*256;           // 0..511 = 4 queries x 128 ch
        int qq = idx2 >> 7, c = idx2 & 127;
        float v = fmaxf(fmaxf(poolS[(qq*4+0)*128 + c], poolS[(qq*4+1)*128 + c]),
                        fmaxf(poolS[(qq*4+2)*128 + c], poolS[(qq*4+3)*128 + c]));
        g_pool[(size_t)((m0 >> 5) + qq) * C2 + c] = v;
    }
    __syncthreads();                      // pool reads done before redS overwrite

    // ---- BN2 stats (over all pre-BN samples) ----
    float ls[8], lq[8];
    #pragma unroll
    for (int j = 0; j < 8; j++) {
        float s = 0.f, q = 0.f;
        #pragma unroll
        for (int i = 0; i < 8; i++) { float v = acc[i][j]; s += v; q = fmaf(v, v, q); }
        ls[j] = s; lq[j] = q;
    }
    float* redS = sm2;  float* redQ = sm2 + 2048;
    #pragma unroll
    for (int j = 0; j < 8; j++) { redS[ts*128 + o8 + j] = ls[j]; redQ[ts*128 + o8 + j] = lq[j]; }
    __syncthreads();
    if (tid < 128) {
        float s = 0.f, q = 0.f;
        #pragma unroll
        for (int t2 = 0; t2 < 16; t2++) { s += redS[t2*128 + tid]; q += redQ[t2*128 + tid]; }
        atomicAdd(&g_sum[2][tid], s);
        atomicAdd(&g_sq[2][tid],  q);
    }
}

// ---------------- epilogue: BN2 + ReLU on pooled maxima ----------------
__global__ void __launch_bounds__(256) k_out(float* __restrict__ out) {
    const int i = blockIdx.x * 256 + threadIdx.x;   // 0 .. 2M-1
    const int c = i & 127;
    float v = g_pool[i];
    out[(size_t)BB*SS*3 + i] = fmaxf(0.f, fmaf(v, g_bnA[2][c], g_bnB[2][c]));
}

// ---------------- launch ----------------
extern "C" void kernel_launch(void* const* d_in, const int* in_sizes, int n_in,
                              void* d_out, int out_size) {
    const float* xyz = (const float*)d_in[0];
    const float* pts = (const float*)d_in[1];
    const float* W0  = (const float*)d_in[2];
    const float* g0  = (const float*)d_in[3];
    const float* b0  = (const float*)d_in[4];
    const float* W1  = (const float*)d_in[5];
    const float* g1  = (const float*)d_in[6];
    const float* b1  = (const float*)d_in[7];
    const float* W2  = (const float*)d_in[8];
    const float* g2  = (const float*)d_in[9];
    const float* b2  = (const float*)d_in[10];
    float* out = (float*)d_out;

    cudaFuncSetAttribute(k_fps,   cudaFuncAttributeMaxDynamicSharedMemorySize, 65536);
    cudaFuncSetAttribute(k_knn,   cudaFuncAttributeMaxDynamicSharedMemorySize, 65536);
    cudaFuncSetAttribute(k_gemm0, cudaFuncAttributeMaxDynamicSharedMemorySize, 85760);
    cudaFuncSetAttribute(k_gemm1, cudaFuncAttributeMaxDynamicSharedMemorySize, 82944);
    cudaFuncSetAttribute(k_gemm2, cudaFuncAttributeMaxDynamicSharedMemorySize, 66048);

    // launch #4 (1-based) is the profiled one -> k_gemm0 this round
    k_zero<<<1, 128>>>();
    k_fps<<<BB, 256, 65536>>>(xyz, out);
    k_knn<<<(BB*SS)/16, 512, 65536>>>(xyz);
    k_gemm0<<<MM/256, 256, 85760>>>(xyz, pts, W0);
    k_finalize<<<1, 128>>>(0, 64, g0, b0);
    k_gemm1<<<MM/256, 256, 82944>>>(W1);
    k_finalize<<<1, 128>>>(1, 64, g1, b1);
    k_gemm2<<<MM/128, 256, 66048>>>(W2);
    k_finalize<<<1, 128>>>(2, 128, g2, b2);
    k_out<<<(BB*SS*C2)/256, 256>>>(out);
}